// round 4
// baseline (speedup 1.0000x reference)
#include <cuda_runtime.h>
#include <cuda_bf16.h>

typedef unsigned long long ULL;

// ---------------- scratch (static device allocations; no cudaMalloc) -------
__device__ float g_xproj[67108864];   // [2][16384][2048]  268 MB
__device__ float g_h[16777216];       // [b*512+t][1024]   64 MB  (fwd 0:512, bwd 512:1024)
__device__ float g_c[2 * 32 * 512];   // cell state per dir/batch/hidden
__device__ float g_emis[16384 * 32];  // emissions
__device__ float g_llh[32];           // per-batch log-likelihood

// ---------------- helpers ---------------------------------------------------
__device__ __forceinline__ void ffma2(ULL& d, ULL a, ULL b) {
    asm("fma.rn.f32x2 %0, %1, %2, %0;" : "+l"(d) : "l"(a), "l"(b));
}
__device__ __forceinline__ float pairsum(ULL v) {
    float lo = __uint_as_float((unsigned)(v & 0xffffffffull));
    float hi = __uint_as_float((unsigned)(v >> 32));
    return lo + hi;
}

// ---------------- 1) input projection: xproj = X @ W_ih^T + b ---------------
// X: (16384,1024)  W: (2048,1024)  C: (16384,2048) per direction (blockIdx.z)
__global__ __launch_bounds__(256) void proj_kernel(
    const float* __restrict__ A, const float* __restrict__ Wf,
    const float* __restrict__ Wb, const float* __restrict__ bf,
    const float* __restrict__ bb)
{
    __shared__ __align__(16) float As[128 * 34];
    __shared__ __align__(16) float Bs[128 * 34];
    const int d = blockIdx.z;
    const float* W = d ? Wb : Wf;
    const float* bias = d ? bb : bf;
    float* C = g_xproj + (size_t)d * (16384ull * 2048ull);
    const int m0 = blockIdx.y * 128;
    const int n0 = blockIdx.x * 128;
    const int tid = threadIdx.x;
    const int tn = tid & 15;        // n lane (interleaved micro-tile: n = n0 + tn + 16*j)
    const int tm = tid >> 4;        // m lane (m = m0 + tm + 16*i)

    ULL acc[8][8];
#pragma unroll
    for (int i = 0; i < 8; i++)
#pragma unroll
        for (int j = 0; j < 8; j++) acc[i][j] = 0ull;

    for (int kt = 0; kt < 32; kt++) {
        // stage 128x32 tiles of A and W
#pragma unroll
        for (int it = 0; it < 4; it++) {
            int i4 = tid + 256 * it;           // 0..1023
            int row = i4 >> 3;
            int c4 = (i4 & 7) * 4;
            float4 va = *(const float4*)(A + (size_t)(m0 + row) * 1024 + kt * 32 + c4);
            float* sa = As + row * 34 + c4;
            sa[0] = va.x; sa[1] = va.y; sa[2] = va.z; sa[3] = va.w;
            float4 vb = *(const float4*)(W + (size_t)(n0 + row) * 1024 + kt * 32 + c4);
            float* sb = Bs + row * 34 + c4;
            sb[0] = vb.x; sb[1] = vb.y; sb[2] = vb.z; sb[3] = vb.w;
        }
        __syncthreads();
#pragma unroll
        for (int kp = 0; kp < 16; kp++) {
            const int k = kp * 2;
            ULL a2[8], b2[8];
#pragma unroll
            for (int i = 0; i < 8; i++) a2[i] = *(const ULL*)(As + (tm + 16 * i) * 34 + k);
#pragma unroll
            for (int j = 0; j < 8; j++) b2[j] = *(const ULL*)(Bs + (tn + 16 * j) * 34 + k);
#pragma unroll
            for (int i = 0; i < 8; i++)
#pragma unroll
                for (int j = 0; j < 8; j++) ffma2(acc[i][j], a2[i], b2[j]);
        }
        __syncthreads();
    }
    // epilogue: pair-sum + bias, coalesced stores (n = n0 + tn + 16*j)
#pragma unroll
    for (int i = 0; i < 8; i++) {
        const int cm = m0 + tm + 16 * i;
        float* crow = C + (size_t)cm * 2048 + n0;
#pragma unroll
        for (int j = 0; j < 8; j++) {
            int nn = tn + 16 * j;
            crow[nn] = pairsum(acc[i][j]) + bias[n0 + nn];
        }
    }
}

// ---------------- 2) one LSTM time step, both directions ---------------------
// grid: 128 CTAs. blk>>6 = dir, blk&63 = j (hidden slice of 8 units).
// Per CTA: gates(32 rows x 32 batch) = h_prev(32x512) @ Whh_slice^T + xproj,
// then the cell update for its 8 hidden units.
#define LSTM_SMEM ((32 * 514 + 8 * 32 * 32 + 32 * 33) * 4)

__global__ __launch_bounds__(256) void lstm_step_kernel(
    const float* __restrict__ whf, const float* __restrict__ whb, int s)
{
    extern __shared__ float sm[];
    float* h_s  = sm;                  // [32][514] padded h_prev
    float* part = sm + 32 * 514;       // [8][32][32] k-split partials
    float* gsum = part + 8192;         // [32][33] reduced gates

    const int blk = blockIdx.x;
    const int d = blk >> 6;
    const int j = blk & 63;
    const int tid = threadIdx.x;
    const float* w = d ? whb : whf;
    const int t = d ? (511 - s) : s;

    // ---- load h_prev for this direction into smem (zeros at s==0)
    if (s > 0) {
        const int tp = d ? (512 - s) : (s - 1);
        const float* hbase = g_h + (size_t)tp * 1024 + (size_t)d * 512;
#pragma unroll
        for (int it = 0; it < 16; it++) {
            int i4 = tid + 256 * it;          // 0..4095
            int b = i4 >> 7;
            int kk = (i4 & 127) * 4;
            float4 v = *(const float4*)(hbase + (size_t)b * 512 * 1024 + kk);
            float* hp = h_s + b * 514 + kk;
            hp[0] = v.x; hp[1] = v.y; hp[2] = v.z; hp[3] = v.w;
        }
    } else {
        for (int i = tid; i < 32 * 514; i += 256) h_s[i] = 0.f;
    }
    __syncthreads();

    // ---- GEMM: thread = (warp=k-split ks, lane -> rg gate, bg batch-group)
    const int warp = tid >> 5;           // ks: k range [warp*64, warp*64+64)
    const int lane = tid & 31;
    const int bg = lane & 7;             // batches {bg, bg+8, bg+16, bg+24}
    const int rg = lane >> 3;            // gate index q (rows 512*q+8j .. +8)
    const float* wbase = w + (size_t)(512 * rg + 8 * j) * 512 + warp * 64;
    const float* hb2 = h_s + bg * 514 + warp * 64;

    ULL acc[8][4];
#pragma unroll
    for (int ri = 0; ri < 8; ri++)
#pragma unroll
        for (int bi = 0; bi < 4; bi++) acc[ri][bi] = 0ull;

#pragma unroll
    for (int kq = 0; kq < 16; kq++) {
        float4 wq[8];
#pragma unroll
        for (int ri = 0; ri < 8; ri++)
            wq[ri] = *(const float4*)(wbase + ri * 512 + kq * 4);
#pragma unroll
        for (int half = 0; half < 2; half++) {
            ULL h2[4];
#pragma unroll
            for (int bi = 0; bi < 4; bi++)
                h2[bi] = *(const ULL*)(hb2 + bi * 8 * 514 + kq * 4 + half * 2);
#pragma unroll
            for (int ri = 0; ri < 8; ri++) {
                ULL w2 = ((const ULL*)&wq[ri])[half];
#pragma unroll
                for (int bi = 0; bi < 4; bi++) ffma2(acc[ri][bi], w2, h2[bi]);
            }
        }
    }
#pragma unroll
    for (int ri = 0; ri < 8; ri++) {
        const int lr = rg * 8 + ri;
#pragma unroll
        for (int bi = 0; bi < 4; bi++) {
            const int b = bg + 8 * bi;
            part[(warp * 32 + lr) * 32 + b] = pairsum(acc[ri][bi]);
        }
    }
    __syncthreads();

    // ---- reduce k-splits + add xproj
    {
        const float* xp = g_xproj + (size_t)d * (16384ull * 2048ull);
#pragma unroll
        for (int rr = 0; rr < 4; rr++) {
            int o = tid + 256 * rr;        // 0..1023
            int lr = o >> 5;
            int b = o & 31;
            float v = 0.f;
#pragma unroll
            for (int ks = 0; ks < 8; ks++) v += part[ks * 1024 + o];
            int grow = 512 * (lr >> 3) + 8 * j + (lr & 7);
            v += xp[((size_t)b * 512 + t) * 2048 + grow];
            gsum[lr * 33 + b] = v;
        }
    }
    __syncthreads();

    // ---- cell update (8 hidden units x 32 batches)
    {
        const int u = tid & 7;
        const int b = tid >> 3;
        float gi = gsum[(0 * 8 + u) * 33 + b];
        float gf = gsum[(1 * 8 + u) * 33 + b];
        float gg = gsum[(2 * 8 + u) * 33 + b];
        float go = gsum[(3 * 8 + u) * 33 + b];
        float si = 1.f / (1.f + __expf(-gi));
        float sf = 1.f / (1.f + __expf(-gf));
        float so = 1.f / (1.f + __expf(-go));
        float tg = tanhf(gg);
        size_t ci = ((size_t)d * 32 + b) * 512 + 8 * j + u;
        float c_old = (s > 0) ? g_c[ci] : 0.f;
        float c_new = sf * c_old + si * tg;
        g_c[ci] = c_new;
        float hv = so * tanhf(c_new);
        g_h[((size_t)b * 512 + t) * 1024 + d * 512 + 8 * j + u] = hv;
    }
}

// ---------------- 3) LayerNorm + emissions -----------------------------------
__global__ __launch_bounds__(256) void ln_emis_kernel(
    const float* __restrict__ lng, const float* __restrict__ lnb,
    const float* __restrict__ Wt, const float* __restrict__ bt)
{
    __shared__ float shn[1024];
    __shared__ float red[16];
    const int row = blockIdx.x;
    const int tid = threadIdx.x;
    const float* hp = g_h + (size_t)row * 1024;
    float4 v = *(const float4*)(hp + tid * 4);
    float s1 = v.x + v.y + v.z + v.w;
    float s2 = v.x * v.x + v.y * v.y + v.z * v.z + v.w * v.w;
#pragma unroll
    for (int o = 16; o; o >>= 1) {
        s1 += __shfl_down_sync(0xffffffffu, s1, o);
        s2 += __shfl_down_sync(0xffffffffu, s2, o);
    }
    const int w = tid >> 5, ln = tid & 31;
    if (ln == 0) { red[w] = s1; red[8 + w] = s2; }
    __syncthreads();
    if (tid == 0) {
        float a = 0.f, bq = 0.f;
#pragma unroll
        for (int i = 0; i < 8; i++) { a += red[i]; bq += red[8 + i]; }
        float mu = a * (1.f / 1024.f);
        float var = bq * (1.f / 1024.f) - mu * mu;
        red[0] = mu;
        red[1] = rsqrtf(var + 1e-5f);
    }
    __syncthreads();
    const float mu = red[0], rs = red[1];
    float4 g4 = *(const float4*)(lng + tid * 4);
    float4 b4 = *(const float4*)(lnb + tid * 4);
    shn[tid * 4 + 0] = (v.x - mu) * rs * g4.x + b4.x;
    shn[tid * 4 + 1] = (v.y - mu) * rs * g4.y + b4.y;
    shn[tid * 4 + 2] = (v.z - mu) * rs * g4.z + b4.z;
    shn[tid * 4 + 3] = (v.w - mu) * rs * g4.w + b4.w;
    __syncthreads();
    // emissions: 8 warps x 4 tags
#pragma unroll
    for (int tt = 0; tt < 4; tt++) {
        const int tag = w * 4 + tt;
        const float* wrow = Wt + (size_t)tag * 1024;
        float acc = 0.f;
#pragma unroll
        for (int i = 0; i < 32; i++) acc += shn[ln + 32 * i] * wrow[ln + 32 * i];
#pragma unroll
        for (int o = 16; o; o >>= 1) acc += __shfl_down_sync(0xffffffffu, acc, o);
        if (ln == 0) g_emis[(size_t)row * 32 + tag] = acc + bt[tag];
    }
}

// ---------------- 4) CRF log-likelihood (one warp per batch) -----------------
// NOTE: target_tag arrives as int32 (JAX x64 disabled downcasts jnp.int64).
__global__ void crf_kernel(const int* __restrict__ tags,
                           const int* __restrict__ mask,
                           const float* __restrict__ trans,
                           const float* __restrict__ st,
                           const float* __restrict__ en)
{
    __shared__ float tr[32 * 33];
    const int b = blockIdx.x;
    const int jx = threadIdx.x;
    for (int i = jx; i < 1024; i += 32) tr[(i >> 5) * 33 + (i & 31)] = trans[i];
    __syncwarp();
    const float* eb = g_emis + (size_t)b * 512 * 32;
    const int* tg = tags + (size_t)b * 512;
    const int* mk = mask + (size_t)b * 512;

    float alpha = st[jx] + eb[jx];
    // numerator + mask-sum (strided over l, warp-reduced)
    float np = 0.f;
    int ms = 0;
    for (int l = jx; l < 512; l += 32) {
        int m = mk[l];
        ms += m;
        if (l > 0 && m) {
            int tp = tg[l - 1], tc = tg[l];
            np += tr[tp * 33 + tc] + eb[l * 32 + tc];
        }
    }
    if (jx == 0) np += st[tg[0]] + eb[tg[0]];
#pragma unroll
    for (int o = 16; o; o >>= 1) {
        np += __shfl_xor_sync(0xffffffffu, np, o);
        ms += __shfl_xor_sync(0xffffffffu, ms, o);
    }
    const int lastidx = ms - 1;
    const float nend = en[tg[lastidx]];

    // forward algorithm
    for (int l = 1; l < 512; l++) {
        float v[32];
        float mx = -1e30f;
#pragma unroll
        for (int i = 0; i < 32; i++) {
            float ai = __shfl_sync(0xffffffffu, alpha, i);
            v[i] = ai + tr[i * 33 + jx];
            mx = fmaxf(mx, v[i]);
        }
        float sa = 0.f;
#pragma unroll
        for (int i = 0; i < 32; i++) sa += __expf(v[i] - mx);
        float anew = mx + __logf(sa) + eb[l * 32 + jx];
        alpha = mk[l] ? anew : alpha;
    }
    float z = alpha + en[jx];
    float mz = z;
#pragma unroll
    for (int o = 16; o; o >>= 1) mz = fmaxf(mz, __shfl_xor_sync(0xffffffffu, mz, o));
    float sz = __expf(z - mz);
#pragma unroll
    for (int o = 16; o; o >>= 1) sz += __shfl_xor_sync(0xffffffffu, sz, o);
    float logZ = mz + __logf(sz);
    if (jx == 0) g_llh[b] = np + nend - logZ;
}

// ---------------- 5) final reduce --------------------------------------------
__global__ void final_kernel(float* out) {
    float v = g_llh[threadIdx.x];
#pragma unroll
    for (int o = 16; o; o >>= 1) v += __shfl_xor_sync(0xffffffffu, v, o);
    if (threadIdx.x == 0) out[0] = -v * (1.f / 32.f);
}

// ---------------- launch ------------------------------------------------------
extern "C" void kernel_launch(void* const* d_in, const int* in_sizes, int n_in,
                              void* d_out, int out_size) {
    const float*     x     = (const float*)d_in[0];
    const int*       tags  = (const int*)d_in[1];   // int32 (JAX x64 disabled)
    const int*       mask  = (const int*)d_in[2];
    const float*     wihf  = (const float*)d_in[3];
    const float*     whhf  = (const float*)d_in[4];
    const float*     bf    = (const float*)d_in[5];
    const float*     wihb  = (const float*)d_in[6];
    const float*     whhb  = (const float*)d_in[7];
    const float*     bb    = (const float*)d_in[8];
    const float*     lng   = (const float*)d_in[9];
    const float*     lnb   = (const float*)d_in[10];
    const float*     Wt    = (const float*)d_in[11];
    const float*     bt    = (const float*)d_in[12];
    const float*     trans = (const float*)d_in[13];
    const float*     st    = (const float*)d_in[14];
    const float*     en    = (const float*)d_in[15];
    float* out = (float*)d_out;

    cudaFuncSetAttribute(lstm_step_kernel,
                         cudaFuncAttributeMaxDynamicSharedMemorySize, LSTM_SMEM);

    proj_kernel<<<dim3(16, 128, 2), 256>>>(x, wihf, wihb, bf, bb);
    for (int s = 0; s < 512; s++)
        lstm_step_kernel<<<128, 256, LSTM_SMEM>>>(whhf, whhb, s);
    ln_emis_kernel<<<16384, 256>>>(lng, lnb, Wt, bt);
    crf_kernel<<<32, 32>>>(tags, mask, trans, st, en);
    final_kernel<<<1, 32>>>(out);
    (void)in_sizes; (void)n_in; (void)out_size;
}

// round 7
// speedup vs baseline: 1.0488x; 1.0488x over previous
#include <cuda_runtime.h>
#include <cuda_bf16.h>

typedef unsigned long long ULL;

// ---------------- scratch (static device allocations; no cudaMalloc) -------
__device__ float g_xproj[67108864];   // [2][16384][2048]  268 MB
__device__ float g_h[16777216];       // [b*512+t][1024]   64 MB  (fwd 0:512, bwd 512:1024)
__device__ float g_emis[16384 * 32];  // emissions
__device__ float g_llh[32];           // per-batch log-likelihood
__device__ unsigned g_cnt[2];         // per-direction arrival counters

// ---------------- helpers ---------------------------------------------------
__device__ __forceinline__ void ffma2(ULL& d, ULL a, ULL b) {
    asm("fma.rn.f32x2 %0, %1, %2, %0;" : "+l"(d) : "l"(a), "l"(b));
}
__device__ __forceinline__ float pairsum(ULL v) {
    float lo = __uint_as_float((unsigned)(v & 0xffffffffull));
    float hi = __uint_as_float((unsigned)(v >> 32));
    return lo + hi;
}

// ---------------- 1) input projection: xproj = X @ W_ih^T + b ---------------
__global__ __launch_bounds__(256) void proj_kernel(
    const float* __restrict__ A, const float* __restrict__ Wf,
    const float* __restrict__ Wb, const float* __restrict__ bf,
    const float* __restrict__ bb)
{
    __shared__ __align__(16) float As[128 * 34];
    __shared__ __align__(16) float Bs[128 * 34];
    const int d = blockIdx.z;
    const float* W = d ? Wb : Wf;
    const float* bias = d ? bb : bf;
    float* C = g_xproj + (size_t)d * (16384ull * 2048ull);
    const int m0 = blockIdx.y * 128;
    const int n0 = blockIdx.x * 128;
    const int tid = threadIdx.x;
    const int tn = tid & 15;
    const int tm = tid >> 4;

    ULL acc[8][8];
#pragma unroll
    for (int i = 0; i < 8; i++)
#pragma unroll
        for (int j = 0; j < 8; j++) acc[i][j] = 0ull;

    for (int kt = 0; kt < 32; kt++) {
#pragma unroll
        for (int it = 0; it < 4; it++) {
            int i4 = tid + 256 * it;
            int row = i4 >> 3;
            int c4 = (i4 & 7) * 4;
            float4 va = *(const float4*)(A + (size_t)(m0 + row) * 1024 + kt * 32 + c4);
            float* sa = As + row * 34 + c4;
            sa[0] = va.x; sa[1] = va.y; sa[2] = va.z; sa[3] = va.w;
            float4 vb = *(const float4*)(W + (size_t)(n0 + row) * 1024 + kt * 32 + c4);
            float* sb = Bs + row * 34 + c4;
            sb[0] = vb.x; sb[1] = vb.y; sb[2] = vb.z; sb[3] = vb.w;
        }
        __syncthreads();
#pragma unroll
        for (int kp = 0; kp < 16; kp++) {
            const int k = kp * 2;
            ULL a2[8], b2[8];
#pragma unroll
            for (int i = 0; i < 8; i++) a2[i] = *(const ULL*)(As + (tm + 16 * i) * 34 + k);
#pragma unroll
            for (int j = 0; j < 8; j++) b2[j] = *(const ULL*)(Bs + (tn + 16 * j) * 34 + k);
#pragma unroll
            for (int i = 0; i < 8; i++)
#pragma unroll
                for (int j = 0; j < 8; j++) ffma2(acc[i][j], a2[i], b2[j]);
        }
        __syncthreads();
    }
#pragma unroll
    for (int i = 0; i < 8; i++) {
        const int cm = m0 + tm + 16 * i;
        float* crow = C + (size_t)cm * 2048 + n0;
#pragma unroll
        for (int j = 0; j < 8; j++) {
            int nn = tn + 16 * j;
            crow[nn] = pairsum(acc[i][j]) + bias[n0 + nn];
        }
    }
}

// ---------------- counter reset ---------------------------------------------
__global__ void zero_cnt_kernel() { g_cnt[threadIdx.x] = 0u; }

// ---------------- 2) persistent BiLSTM recurrence ----------------------------
// 128 CTAs (all co-resident, 1/SM). blk>>6 = dir d, blk&63 = j (8 hidden units).
// Weights (32 gate rows x 512) staged to smem ONCE; cell state in registers;
// per-direction grid barrier via monotonic counter in L2.
//
// smem layout (floats):
//   ws   [0, 16520)     weight slice, row stride 516 + (rg*4) bank shift
//   h_s  [16520, +16448) h_prev [32][514]
//   part [.., +8192)     k-split partials [8][32][32]
//   gsum [.., +1056)     reduced gates [32][33]
#define WS_OFF   0
#define H_OFF    16520
#define PART_OFF (16520 + 16448)
#define GSUM_OFF (16520 + 16448 + 8192)
#define PERSIST_SMEM ((16520 + 16448 + 8192 + 1056) * 4)

__global__ __launch_bounds__(256, 1) void lstm_persist_kernel(
    const float* __restrict__ whf, const float* __restrict__ whb)
{
    extern __shared__ float sm[];
    float* ws   = sm + WS_OFF;
    float* h_s  = sm + H_OFF;
    float* part = sm + PART_OFF;
    float* gsum = sm + GSUM_OFF;

    const int blk = blockIdx.x;
    const int d = blk >> 6;
    const int j = blk & 63;
    const int tid = threadIdx.x;
    const float* w = d ? whb : whf;

    // ---- stage weight slice into smem (once) --------------------------------
#pragma unroll
    for (int it = 0; it < 16; it++) {
        int idx4 = tid + 256 * it;          // 0..4095
        int i = idx4 * 4;
        int lr = i >> 9;                     // 0..31
        int k = i & 511;
        int rowg = 512 * (lr >> 3) + 8 * j + (lr & 7);
        float4 v = *(const float4*)(w + (size_t)rowg * 512 + k);
        float* p = ws + lr * 516 + (lr >> 3) * 4 + k;
        p[0] = v.x; p[1] = v.y; p[2] = v.z; p[3] = v.w;
    }

    // GEMM thread roles
    const int warp = tid >> 5;              // k-split: [warp*64, +64)
    const int lane = tid & 31;
    const int bg = lane & 7;                // batch group
    const int rg = lane >> 3;               // gate index
    const float* xp = g_xproj + (size_t)d * (16384ull * 2048ull);

    // cell update role (one (unit,batch) per thread) — c lives in a register
    const int cu = tid & 7;
    const int cb = tid >> 3;
    float c_reg = 0.f;

    volatile unsigned* cntp = &g_cnt[d];
    __syncthreads();

    for (int s = 0; s < 512; s++) {
        const int t = d ? (511 - s) : s;

        // ---- wait for previous step of this direction -----------------------
        if (s > 0) {
            if (tid == 0) {
                const unsigned target = 64u * (unsigned)s;
                while (*cntp < target) { }
                __threadfence();
            }
            __syncthreads();
            // ---- stage h_prev
            const int tp = d ? (512 - s) : (s - 1);
            const float* hbase = g_h + (size_t)tp * 1024 + (size_t)d * 512;
#pragma unroll
            for (int it = 0; it < 16; it++) {
                int i4 = tid + 256 * it;          // 0..4095
                int b = i4 >> 7;
                int kk = (i4 & 127) * 4;
                float4 v = __ldcg((const float4*)(hbase + (size_t)b * 512 * 1024 + kk));
                float* hp = h_s + b * 514 + kk;
                hp[0] = v.x; hp[1] = v.y; hp[2] = v.z; hp[3] = v.w;
            }
        } else {
            for (int i = tid; i < 32 * 514; i += 256) h_s[i] = 0.f;
        }
        __syncthreads();

        // ---- GEMM: gates += h_prev @ Whh_slice^T (weights from smem) --------
        {
            const float* wbase = ws + (rg * 8) * 516 + rg * 4 + warp * 64;
            const float* hb2 = h_s + bg * 514 + warp * 64;

            ULL acc[8][4];
#pragma unroll
            for (int ri = 0; ri < 8; ri++)
#pragma unroll
                for (int bi = 0; bi < 4; bi++) acc[ri][bi] = 0ull;

#pragma unroll
            for (int kq = 0; kq < 16; kq++) {
                float4 wq[8];
#pragma unroll
                for (int ri = 0; ri < 8; ri++)
                    wq[ri] = *(const float4*)(wbase + ri * 516 + kq * 4);
#pragma unroll
                for (int half = 0; half < 2; half++) {
                    ULL h2[4];
#pragma unroll
                    for (int bi = 0; bi < 4; bi++)
                        h2[bi] = *(const ULL*)(hb2 + bi * 8 * 514 + kq * 4 + half * 2);
#pragma unroll
                    for (int ri = 0; ri < 8; ri++) {
                        ULL w2 = ((const ULL*)&wq[ri])[half];
#pragma unroll
                        for (int bi = 0; bi < 4; bi++) ffma2(acc[ri][bi], w2, h2[bi]);
                    }
                }
            }
#pragma unroll
            for (int ri = 0; ri < 8; ri++) {
                const int lr = rg * 8 + ri;
#pragma unroll
                for (int bi = 0; bi < 4; bi++) {
                    const int b = bg + 8 * bi;
                    part[(warp * 32 + lr) * 32 + b] = pairsum(acc[ri][bi]);
                }
            }
        }
        __syncthreads();

        // ---- reduce k-splits + add xproj ------------------------------------
#pragma unroll
        for (int rr = 0; rr < 4; rr++) {
            int o = tid + 256 * rr;
            int lr = o >> 5;
            int b = o & 31;
            float v = 0.f;
#pragma unroll
            for (int ks = 0; ks < 8; ks++) v += part[ks * 1024 + o];
            int grow = 512 * (lr >> 3) + 8 * j + (lr & 7);
            v += xp[((size_t)b * 512 + t) * 2048 + grow];
            gsum[lr * 33 + b] = v;
        }
        __syncthreads();

        // ---- cell update ----------------------------------------------------
        {
            float gi = gsum[(0 * 8 + cu) * 33 + cb];
            float gf = gsum[(1 * 8 + cu) * 33 + cb];
            float gg = gsum[(2 * 8 + cu) * 33 + cb];
            float go = gsum[(3 * 8 + cu) * 33 + cb];
            float si = 1.f / (1.f + __expf(-gi));
            float sf = 1.f / (1.f + __expf(-gf));
            float so = 1.f / (1.f + __expf(-go));
            float tg = tanhf(gg);
            c_reg = sf * c_reg + si * tg;
            float hv = so * tanhf(c_reg);
            g_h[((size_t)cb * 512 + t) * 1024 + d * 512 + 8 * j + cu] = hv;
        }

        // ---- publish: fence + arrive ----------------------------------------
        __threadfence();
        __syncthreads();
        if (tid == 0) atomicAdd(&g_cnt[d], 1u);
        __syncthreads();
    }
}

// ---------------- 3) LayerNorm + emissions -----------------------------------
__global__ __launch_bounds__(256) void ln_emis_kernel(
    const float* __restrict__ lng, const float* __restrict__ lnb,
    const float* __restrict__ Wt, const float* __restrict__ bt)
{
    __shared__ float shn[1024];
    __shared__ float red[16];
    const int row = blockIdx.x;
    const int tid = threadIdx.x;
    const float* hp = g_h + (size_t)row * 1024;
    float4 v = *(const float4*)(hp + tid * 4);
    float s1 = v.x + v.y + v.z + v.w;
    float s2 = v.x * v.x + v.y * v.y + v.z * v.z + v.w * v.w;
#pragma unroll
    for (int o = 16; o; o >>= 1) {
        s1 += __shfl_down_sync(0xffffffffu, s1, o);
        s2 += __shfl_down_sync(0xffffffffu, s2, o);
    }
    const int w = tid >> 5, ln = tid & 31;
    if (ln == 0) { red[w] = s1; red[8 + w] = s2; }
    __syncthreads();
    if (tid == 0) {
        float a = 0.f, bq = 0.f;
#pragma unroll
        for (int i = 0; i < 8; i++) { a += red[i]; bq += red[8 + i]; }
        float mu = a * (1.f / 1024.f);
        float var = bq * (1.f / 1024.f) - mu * mu;
        red[0] = mu;
        red[1] = rsqrtf(var + 1e-5f);
    }
    __syncthreads();
    const float mu = red[0], rs = red[1];
    float4 g4 = *(const float4*)(lng + tid * 4);
    float4 b4 = *(const float4*)(lnb + tid * 4);
    shn[tid * 4 + 0] = (v.x - mu) * rs * g4.x + b4.x;
    shn[tid * 4 + 1] = (v.y - mu) * rs * g4.y + b4.y;
    shn[tid * 4 + 2] = (v.z - mu) * rs * g4.z + b4.z;
    shn[tid * 4 + 3] = (v.w - mu) * rs * g4.w + b4.w;
    __syncthreads();
#pragma unroll
    for (int tt = 0; tt < 4; tt++) {
        const int tag = w * 4 + tt;
        const float* wrow = Wt + (size_t)tag * 1024;
        float acc = 0.f;
#pragma unroll
        for (int i = 0; i < 32; i++) acc += shn[ln + 32 * i] * wrow[ln + 32 * i];
#pragma unroll
        for (int o = 16; o; o >>= 1) acc += __shfl_down_sync(0xffffffffu, acc, o);
        if (ln == 0) g_emis[(size_t)row * 32 + tag] = acc + bt[tag];
    }
}

// ---------------- 4) CRF log-likelihood (one warp per batch) -----------------
__global__ void crf_kernel(const int* __restrict__ tags,
                           const int* __restrict__ mask,
                           const float* __restrict__ trans,
                           const float* __restrict__ st,
                           const float* __restrict__ en)
{
    __shared__ float tr[32 * 33];
    const int b = blockIdx.x;
    const int jx = threadIdx.x;
    for (int i = jx; i < 1024; i += 32) tr[(i >> 5) * 33 + (i & 31)] = trans[i];
    __syncwarp();
    const float* eb = g_emis + (size_t)b * 512 * 32;
    const int* tg = tags + (size_t)b * 512;
    const int* mk = mask + (size_t)b * 512;

    float alpha = st[jx] + eb[jx];
    float np = 0.f;
    int ms = 0;
    for (int l = jx; l < 512; l += 32) {
        int m = mk[l];
        ms += m;
        if (l > 0 && m) {
            int tp = tg[l - 1], tc = tg[l];
            np += tr[tp * 33 + tc] + eb[l * 32 + tc];
        }
    }
    if (jx == 0) np += st[tg[0]] + eb[tg[0]];
#pragma unroll
    for (int o = 16; o; o >>= 1) {
        np += __shfl_xor_sync(0xffffffffu, np, o);
        ms += __shfl_xor_sync(0xffffffffu, ms, o);
    }
    const int lastidx = ms - 1;
    const float nend = en[tg[lastidx]];

    for (int l = 1; l < 512; l++) {
        float v[32];
        float mx = -1e30f;
#pragma unroll
        for (int i = 0; i < 32; i++) {
            float ai = __shfl_sync(0xffffffffu, alpha, i);
            v[i] = ai + tr[i * 33 + jx];
            mx = fmaxf(mx, v[i]);
        }
        float sa = 0.f;
#pragma unroll
        for (int i = 0; i < 32; i++) sa += __expf(v[i] - mx);
        float anew = mx + __logf(sa) + eb[l * 32 + jx];
        alpha = mk[l] ? anew : alpha;
    }
    float z = alpha + en[jx];
    float mz = z;
#pragma unroll
    for (int o = 16; o; o >>= 1) mz = fmaxf(mz, __shfl_xor_sync(0xffffffffu, mz, o));
    float sz = __expf(z - mz);
#pragma unroll
    for (int o = 16; o; o >>= 1) sz += __shfl_xor_sync(0xffffffffu, sz, o);
    float logZ = mz + __logf(sz);
    if (jx == 0) g_llh[b] = np + nend - logZ;
}

// ---------------- 5) final reduce --------------------------------------------
__global__ void final_kernel(float* out) {
    float v = g_llh[threadIdx.x];
#pragma unroll
    for (int o = 16; o; o >>= 1) v += __shfl_xor_sync(0xffffffffu, v, o);
    if (threadIdx.x == 0) out[0] = -v * (1.f / 32.f);
}

// ---------------- launch ------------------------------------------------------
extern "C" void kernel_launch(void* const* d_in, const int* in_sizes, int n_in,
                              void* d_out, int out_size) {
    const float* x     = (const float*)d_in[0];
    const int*   tags  = (const int*)d_in[1];   // int32 (JAX x64 disabled)
    const int*   mask  = (const int*)d_in[2];
    const float* wihf  = (const float*)d_in[3];
    const float* whhf  = (const float*)d_in[4];
    const float* bf    = (const float*)d_in[5];
    const float* wihb  = (const float*)d_in[6];
    const float* whhb  = (const float*)d_in[7];
    const float* bb    = (const float*)d_in[8];
    const float* lng   = (const float*)d_in[9];
    const float* lnb   = (const float*)d_in[10];
    const float* Wt    = (const float*)d_in[11];
    const float* bt    = (const float*)d_in[12];
    const float* trans = (const float*)d_in[13];
    const float* st    = (const float*)d_in[14];
    const float* en    = (const float*)d_in[15];
    float* out = (float*)d_out;

    cudaFuncSetAttribute(lstm_persist_kernel,
                         cudaFuncAttributeMaxDynamicSharedMemorySize, PERSIST_SMEM);

    proj_kernel<<<dim3(16, 128, 2), 256>>>(x, wihf, wihb, bf, bb);
    zero_cnt_kernel<<<1, 2>>>();
    lstm_persist_kernel<<<128, 256, PERSIST_SMEM>>>(whhf, whhb);
    ln_emis_kernel<<<16384, 256>>>(lng, lnb, Wt, bt);
    crf_kernel<<<32, 32>>>(tags, mask, trans, st, en);
    final_kernel<<<1, 32>>>(out);
    (void)in_sizes; (void)n_in; (void)out_size;
}

// round 10
// speedup vs baseline: 1.6731x; 1.5952x over previous
#include <cuda_runtime.h>
#include <cuda_bf16.h>
#include <cstdint>

typedef unsigned long long ULL;

// ---------------- scratch (static device allocations; no cudaMalloc) -------
__device__ float g_xproj[67108864];           // [2][16384][2048] fp32
__device__ float g_h[16777216];               // [b*512+t][1024]
__device__ float g_emis[16384 * 32];
__device__ float g_llh[32];
__device__ unsigned g_cnt[2];
__device__ __nv_bfloat16 g_xb[16777216];      // X in bf16 [16384][1024]
__device__ __nv_bfloat16 g_wb[2][2097152];    // W_ih in bf16 [2][2048][1024]

// ---------------- helpers ---------------------------------------------------
__device__ __forceinline__ void ffma2(ULL& d, ULL a, ULL b) {
    asm("fma.rn.f32x2 %0, %1, %2, %0;" : "+l"(d) : "l"(a), "l"(b));
}
__device__ __forceinline__ float pairsum(ULL v) {
    float lo = __uint_as_float((unsigned)(v & 0xffffffffull));
    float hi = __uint_as_float((unsigned)(v >> 32));
    return lo + hi;
}
__device__ __forceinline__ uint32_t smem_u32(const void* p) {
    uint32_t a;
    asm("{ .reg .u64 t; cvta.to.shared.u64 t, %1; cvt.u32.u64 %0, t; }" : "=r"(a) : "l"(p));
    return a;
}
__device__ __forceinline__ void cp16(uint32_t s, const void* g) {
    asm volatile("cp.async.cg.shared.global [%0], [%1], 16;" :: "r"(s), "l"(g));
}
#define CP_COMMIT() asm volatile("cp.async.commit_group;")
#define CP_WAIT(n)  asm volatile("cp.async.wait_group %0;" :: "n"(n))
#define LDSM_X4(r0, r1, r2, r3, addr) \
    asm volatile("ldmatrix.sync.aligned.m8n8.x4.shared.b16 {%0,%1,%2,%3}, [%4];" \
                 : "=r"(r0), "=r"(r1), "=r"(r2), "=r"(r3) : "r"(addr))
#define LDSM_X2(r0, r1, addr) \
    asm volatile("ldmatrix.sync.aligned.m8n8.x2.shared.b16 {%0,%1}, [%2];" \
                 : "=r"(r0), "=r"(r1) : "r"(addr))
#define MMA_BF16(c0, c1, c2, c3, a0, a1, a2, a3, b0, b1) \
    asm volatile("mma.sync.aligned.m16n8k16.row.col.f32.bf16.bf16.f32 " \
                 "{%0,%1,%2,%3}, {%4,%5,%6,%7}, {%8,%9}, {%0,%1,%2,%3};" \
                 : "+f"(c0), "+f"(c1), "+f"(c2), "+f"(c3) \
                 : "r"(a0), "r"(a1), "r"(a2), "r"(a3), "r"(b0), "r"(b1))

// ---------------- 0) fp32 -> bf16 conversion prepass -------------------------
__global__ __launch_bounds__(256) void cvt_x_kernel(const float* __restrict__ x) {
    int i8 = (blockIdx.x * 256 + threadIdx.x) * 8;
    float4 a = *(const float4*)(x + i8);
    float4 b = *(const float4*)(x + i8 + 4);
    __nv_bfloat162 o[4];
    o[0].x = __float2bfloat16_rn(a.x); o[0].y = __float2bfloat16_rn(a.y);
    o[1].x = __float2bfloat16_rn(a.z); o[1].y = __float2bfloat16_rn(a.w);
    o[2].x = __float2bfloat16_rn(b.x); o[2].y = __float2bfloat16_rn(b.y);
    o[3].x = __float2bfloat16_rn(b.z); o[3].y = __float2bfloat16_rn(b.w);
    *(uint4*)(g_xb + i8) = *(uint4*)o;
}
__global__ __launch_bounds__(256) void cvt_w_kernel(const float* __restrict__ wf,
                                                    const float* __restrict__ wb) {
    const float* w = blockIdx.y ? wb : wf;
    __nv_bfloat16* o = g_wb[blockIdx.y];
    int i8 = (blockIdx.x * 256 + threadIdx.x) * 8;
    float4 a = *(const float4*)(w + i8);
    float4 b = *(const float4*)(w + i8 + 4);
    __nv_bfloat162 p[4];
    p[0].x = __float2bfloat16_rn(a.x); p[0].y = __float2bfloat16_rn(a.y);
    p[1].x = __float2bfloat16_rn(a.z); p[1].y = __float2bfloat16_rn(a.w);
    p[2].x = __float2bfloat16_rn(b.x); p[2].y = __float2bfloat16_rn(b.y);
    p[3].x = __float2bfloat16_rn(b.z); p[3].y = __float2bfloat16_rn(b.w);
    *(uint4*)(o + i8) = *(uint4*)p;
}

// ---------------- 1) input projection via HMMA mma.sync bf16 -----------------
// Per CTA: C[128m x 128n] = Xb[128x1024] @ Wb[128x1024]^T + bias, fp32 out.
// 16 K-chunks of 64, cp.async double-buffered, XOR-swizzled smem, ldmatrix.
// 8 warps: wm = wid>>2 (64-row m tile), wn = wid&3 (32-col n tile).
#define PROJ_SMEM 65536

__global__ __launch_bounds__(256) void proj_hmma_kernel(
    const float* __restrict__ bf, const float* __restrict__ bb)
{
    extern __shared__ __align__(16) char psm[];
    const uint32_t sbase = smem_u32(psm);

    const int tid = threadIdx.x;
    const int wid = tid >> 5;
    const int lane = tid & 31;
    const int d = blockIdx.z;
    const int n0 = blockIdx.x * 128;
    const int m0 = blockIdx.y * 128;
    const __nv_bfloat16* Wb16 = g_wb[d];
    const float* bias = d ? bb : bf;
    float* C = g_xproj + (size_t)d * (16384ull * 2048ull);

    const int wm = wid >> 2;
    const int wn = wid & 3;

    float c[4][4][4];
#pragma unroll
    for (int mi = 0; mi < 4; mi++)
#pragma unroll
        for (int ni = 0; ni < 4; ni++)
#pragma unroll
            for (int q = 0; q < 4; q++) c[mi][ni][q] = 0.f;

    // stage one K=64 chunk (A:16KB + B:16KB) into buffer `buf`
#define STAGE(kc, buf) do { \
    _Pragma("unroll") \
    for (int i = 0; i < 4; i++) { \
        int u = tid + 256 * i; \
        int row = u >> 3, un = u & 7; \
        uint32_t sw = (uint32_t)((un ^ (row & 7)) * 16); \
        cp16(sbase + (buf) * 32768 + row * 128 + sw, \
             g_xb + (size_t)(m0 + row) * 1024 + (kc) * 64 + un * 8); \
        cp16(sbase + (buf) * 32768 + 16384 + row * 128 + sw, \
             Wb16 + (size_t)(n0 + row) * 1024 + (kc) * 64 + un * 8); \
    } \
    CP_COMMIT(); \
} while (0)

    STAGE(0, 0);
    for (int kc = 0; kc < 16; kc++) {
        const int buf = kc & 1;
        if (kc < 15) { STAGE(kc + 1, buf ^ 1); CP_WAIT(1); }
        else         { CP_WAIT(0); }
        __syncthreads();

        const uint32_t abase = sbase + buf * 32768;
        const uint32_t bbase = abase + 16384;
#pragma unroll
        for (int k16 = 0; k16 < 4; k16++) {
            uint32_t a[4][4];
#pragma unroll
            for (int mi = 0; mi < 4; mi++) {
                int row = wm * 64 + mi * 16 + (lane & 15);
                int un = k16 * 2 + (lane >> 4);
                uint32_t addr = abase + row * 128 + ((un ^ (row & 7)) * 16);
                LDSM_X4(a[mi][0], a[mi][1], a[mi][2], a[mi][3], addr);
            }
            uint32_t b[4][2];
#pragma unroll
            for (int ni = 0; ni < 4; ni++) {
                int row = wn * 32 + ni * 8 + (lane & 7);
                int un = k16 * 2 + ((lane >> 3) & 1);
                uint32_t addr = bbase + row * 128 + ((un ^ (row & 7)) * 16);
                LDSM_X2(b[ni][0], b[ni][1], addr);
            }
#pragma unroll
            for (int mi = 0; mi < 4; mi++)
#pragma unroll
                for (int ni = 0; ni < 4; ni++)
                    MMA_BF16(c[mi][ni][0], c[mi][ni][1], c[mi][ni][2], c[mi][ni][3],
                             a[mi][0], a[mi][1], a[mi][2], a[mi][3],
                             b[ni][0], b[ni][1]);
        }
        __syncthreads();
    }
#undef STAGE

    // epilogue: bias + direct fp32 stores
#pragma unroll
    for (int ni = 0; ni < 4; ni++) {
        const int n = n0 + wn * 32 + ni * 8 + (lane & 3) * 2;
        const float bx = bias[n], by = bias[n + 1];
#pragma unroll
        for (int mi = 0; mi < 4; mi++) {
            const int m = m0 + wm * 64 + mi * 16 + (lane >> 2);
            float2 v0 = make_float2(c[mi][ni][0] + bx, c[mi][ni][1] + by);
            float2 v1 = make_float2(c[mi][ni][2] + bx, c[mi][ni][3] + by);
            *(float2*)(C + (size_t)m * 2048 + n) = v0;
            *(float2*)(C + (size_t)(m + 8) * 2048 + n) = v1;
        }
    }
}

// ---------------- counter reset ---------------------------------------------
__global__ void zero_cnt_kernel() { g_cnt[threadIdx.x] = 0u; }

// ---------------- 2) persistent BiLSTM recurrence (512 threads) --------------
#define WS_OFF   0
#define H_OFF    16520
#define PART_OFF (16520 + 16448)
#define GSUM_OFF (16520 + 16448 + 8192)
#define PERSIST_SMEM ((16520 + 16448 + 8192 + 1056) * 4)

__global__ __launch_bounds__(512, 1) void lstm_persist_kernel(
    const float* __restrict__ whf, const float* __restrict__ whb)
{
    extern __shared__ float sm[];
    float* ws   = sm + WS_OFF;
    float* h_s  = sm + H_OFF;
    float* part = sm + PART_OFF;
    float* gsum = sm + GSUM_OFF;

    const int blk = blockIdx.x;
    const int d = blk >> 6;
    const int j = blk & 63;
    const int tid = threadIdx.x;
    const float* w = d ? whb : whf;

    // ---- stage weight slice into smem (once) --------------------------------
#pragma unroll
    for (int it = 0; it < 8; it++) {
        int idx4 = tid + 512 * it;                  // 0..4095
        int i = idx4 * 4;
        int lr = i >> 9;
        int k = i & 511;
        int rowg = 512 * (lr >> 3) + 8 * j + (lr & 7);
        float4 v = *(const float4*)(w + (size_t)rowg * 512 + k);
        float* p = ws + lr * 516 + (lr >> 3) * 4 + k;
        p[0] = v.x; p[1] = v.y; p[2] = v.z; p[3] = v.w;
    }

    // GEMM roles
    const int warp = tid >> 5;
    const int lane = tid & 31;
    const int ks = warp >> 1;
    const int rh = warp & 1;
    const int bg = lane & 7;
    const int rg2 = lane >> 3;
    const int lr0 = rh * 16 + rg2 * 4;
    const float* wbase = ws + lr0 * 516 + (lr0 >> 3) * 4 + ks * 64;
    const float* hb2 = h_s + bg * 514 + ks * 64;
    const float* xp = g_xproj + (size_t)d * (16384ull * 2048ull);

    const int o0 = tid, o1 = tid + 512;
    const int plr0 = o0 >> 5, pb0 = o0 & 31;
    const int plr1 = o1 >> 5, pb1 = o1 & 31;
    const int pg0 = 512 * (plr0 >> 3) + 8 * j + (plr0 & 7);
    const int pg1 = 512 * (plr1 >> 3) + 8 * j + (plr1 & 7);

    const int cu = tid & 7;
    const int cb = tid >> 3;
    float c_reg = 0.f;

    volatile unsigned* cntp = &g_cnt[d];
    __syncthreads();

    for (int s = 0; s < 512; s++) {
        const int t = d ? (511 - s) : s;

        // prefetch xproj before barrier (DRAM latency hidden under spin)
        float pf0 = xp[((size_t)pb0 * 512 + t) * 2048 + pg0];
        float pf1 = xp[((size_t)pb1 * 512 + t) * 2048 + pg1];

        if (s > 0) {
            if (tid == 0) {
                const unsigned target = 64u * (unsigned)s;
                while (*cntp < target) { }
                __threadfence();
            }
            __syncthreads();
            const int tp = d ? (512 - s) : (s - 1);
            const float* hbase = g_h + (size_t)tp * 1024 + (size_t)d * 512;
#pragma unroll
            for (int it = 0; it < 8; it++) {
                int i4 = tid + 512 * it;
                int b = i4 >> 7;
                int kk = (i4 & 127) * 4;
                float4 v = __ldcg((const float4*)(hbase + (size_t)b * 512 * 1024 + kk));
                float* hp = h_s + b * 514 + kk;
                hp[0] = v.x; hp[1] = v.y; hp[2] = v.z; hp[3] = v.w;
            }
        } else {
            for (int i = tid; i < 32 * 514; i += 512) h_s[i] = 0.f;
        }
        __syncthreads();

        // ---- GEMM: gates += h_prev @ Whh_slice^T ----------------------------
        {
            ULL acc[4][4];
#pragma unroll
            for (int ri = 0; ri < 4; ri++)
#pragma unroll
                for (int bi = 0; bi < 4; bi++) acc[ri][bi] = 0ull;

#pragma unroll
            for (int kq = 0; kq < 16; kq++) {
                float4 wq[4];
#pragma unroll
                for (int ri = 0; ri < 4; ri++)
                    wq[ri] = *(const float4*)(wbase + ri * 516 + kq * 4);
#pragma unroll
                for (int half = 0; half < 2; half++) {
                    ULL h2[4];
#pragma unroll
                    for (int bi = 0; bi < 4; bi++)
                        h2[bi] = *(const ULL*)(hb2 + bi * 4112 + kq * 4 + half * 2);
#pragma unroll
                    for (int ri = 0; ri < 4; ri++) {
                        ULL w2 = ((const ULL*)&wq[ri])[half];
#pragma unroll
                        for (int bi = 0; bi < 4; bi++) ffma2(acc[ri][bi], w2, h2[bi]);
                    }
                }
            }
#pragma unroll
            for (int ri = 0; ri < 4; ri++) {
                const int lr = lr0 + ri;
#pragma unroll
                for (int bi = 0; bi < 4; bi++) {
                    const int b = bg + 8 * bi;
                    part[(ks * 32 + lr) * 32 + b] = pairsum(acc[ri][bi]);
                }
            }
        }
        __syncthreads();

        // ---- reduce k-splits + add prefetched xproj -------------------------
        {
            float v0 = pf0, v1 = pf1;
#pragma unroll
            for (int kk = 0; kk < 8; kk++) v0 += part[kk * 1024 + o0];
#pragma unroll
            for (int kk = 0; kk < 8; kk++) v1 += part[kk * 1024 + o1];
            gsum[plr0 * 33 + pb0] = v0;
            gsum[plr1 * 33 + pb1] = v1;
        }
        __syncthreads();

        // ---- cell update (threads 0..255) -----------------------------------
        if (tid < 256) {
            float gi = gsum[(0 * 8 + cu) * 33 + cb];
            float gf = gsum[(1 * 8 + cu) * 33 + cb];
            float gg = gsum[(2 * 8 + cu) * 33 + cb];
            float go = gsum[(3 * 8 + cu) * 33 + cb];
            float si = 1.f / (1.f + __expf(-gi));
            float sf = 1.f / (1.f + __expf(-gf));
            float so = 1.f / (1.f + __expf(-go));
            float tg = tanhf(gg);
            c_reg = sf * c_reg + si * tg;
            float hv = so * tanhf(c_reg);
            g_h[((size_t)cb * 512 + t) * 1024 + d * 512 + 8 * j + cu] = hv;
        }

        __threadfence();
        __syncthreads();
        if (tid == 0) atomicAdd(&g_cnt[d], 1u);
    }
}

// ---------------- 3) LayerNorm + emissions -----------------------------------
__global__ __launch_bounds__(256) void ln_emis_kernel(
    const float* __restrict__ lng, const float* __restrict__ lnb,
    const float* __restrict__ Wt, const float* __restrict__ bt)
{
    __shared__ float shn[1024];
    __shared__ float red[16];
    const int row = blockIdx.x;
    const int tid = threadIdx.x;
    const float* hp = g_h + (size_t)row * 1024;
    float4 v = *(const float4*)(hp + tid * 4);
    float s1 = v.x + v.y + v.z + v.w;
    float s2 = v.x * v.x + v.y * v.y + v.z * v.z + v.w * v.w;
#pragma unroll
    for (int o = 16; o; o >>= 1) {
        s1 += __shfl_down_sync(0xffffffffu, s1, o);
        s2 += __shfl_down_sync(0xffffffffu, s2, o);
    }
    const int w = tid >> 5, ln = tid & 31;
    if (ln == 0) { red[w] = s1; red[8 + w] = s2; }
    __syncthreads();
    if (tid == 0) {
        float a = 0.f, bq = 0.f;
#pragma unroll
        for (int i = 0; i < 8; i++) { a += red[i]; bq += red[8 + i]; }
        float mu = a * (1.f / 1024.f);
        float var = bq * (1.f / 1024.f) - mu * mu;
        red[0] = mu;
        red[1] = rsqrtf(var + 1e-5f);
    }
    __syncthreads();
    const float mu = red[0], rs = red[1];
    float4 g4 = *(const float4*)(lng + tid * 4);
    float4 b4 = *(const float4*)(lnb + tid * 4);
    shn[tid * 4 + 0] = (v.x - mu) * rs * g4.x + b4.x;
    shn[tid * 4 + 1] = (v.y - mu) * rs * g4.y + b4.y;
    shn[tid * 4 + 2] = (v.z - mu) * rs * g4.z + b4.z;
    shn[tid * 4 + 3] = (v.w - mu) * rs * g4.w + b4.w;
    __syncthreads();
#pragma unroll
    for (int tt = 0; tt < 4; tt++) {
        const int tag = w * 4 + tt;
        const float* wrow = Wt + (size_t)tag * 1024;
        float acc = 0.f;
#pragma unroll
        for (int i = 0; i < 32; i++) acc += shn[ln + 32 * i] * wrow[ln + 32 * i];
#pragma unroll
        for (int o = 16; o; o >>= 1) acc += __shfl_down_sync(0xffffffffu, acc, o);
        if (ln == 0) g_emis[(size_t)row * 32 + tag] = acc + bt[tag];
    }
}

// ---------------- 4) CRF log-likelihood (one warp per batch) -----------------
__global__ void crf_kernel(const int* __restrict__ tags,
                           const int* __restrict__ mask,
                           const float* __restrict__ trans,
                           const float* __restrict__ st,
                           const float* __restrict__ en)
{
    __shared__ float tr[32 * 33];
    const int b = blockIdx.x;
    const int jx = threadIdx.x;
    for (int i = jx; i < 1024; i += 32) tr[(i >> 5) * 33 + (i & 31)] = trans[i];
    __syncwarp();
    const float* eb = g_emis + (size_t)b * 512 * 32;
    const int* tg = tags + (size_t)b * 512;
    const int* mk = mask + (size_t)b * 512;

    float alpha = st[jx] + eb[jx];
    float np = 0.f;
    int ms = 0;
    for (int l = jx; l < 512; l += 32) {
        int m = mk[l];
        ms += m;
        if (l > 0 && m) {
            int tp = tg[l - 1], tc = tg[l];
            np += tr[tp * 33 + tc] + eb[l * 32 + tc];
        }
    }
    if (jx == 0) np += st[tg[0]] + eb[tg[0]];
#pragma unroll
    for (int o = 16; o; o >>= 1) {
        np += __shfl_xor_sync(0xffffffffu, np, o);
        ms += __shfl_xor_sync(0xffffffffu, ms, o);
    }
    const int lastidx = ms - 1;
    const float nend = en[tg[lastidx]];

    for (int l = 1; l < 512; l++) {
        float v[32];
        float mx = -1e30f;
#pragma unroll
        for (int i = 0; i < 32; i++) {
            float ai = __shfl_sync(0xffffffffu, alpha, i);
            v[i] = ai + tr[i * 33 + jx];
            mx = fmaxf(mx, v[i]);
        }
        float sa = 0.f;
#pragma unroll
        for (int i = 0; i < 32; i++) sa += __expf(v[i] - mx);
        float anew = mx + __logf(sa) + eb[l * 32 + jx];
        alpha = mk[l] ? anew : alpha;
    }
    float z = alpha + en[jx];
    float mz = z;
#pragma unroll
    for (int o = 16; o; o >>= 1) mz = fmaxf(mz, __shfl_xor_sync(0xffffffffu, mz, o));
    float sz = __expf(z - mz);
#pragma unroll
    for (int o = 16; o; o >>= 1) sz += __shfl_xor_sync(0xffffffffu, sz, o);
    float logZ = mz + __logf(sz);
    if (jx == 0) g_llh[b] = np + nend - logZ;
}

// ---------------- 5) final reduce --------------------------------------------
__global__ void final_kernel(float* out) {
    float v = g_llh[threadIdx.x];
#pragma unroll
    for (int o = 16; o; o >>= 1) v += __shfl_xor_sync(0xffffffffu, v, o);
    if (threadIdx.x == 0) out[0] = -v * (1.f / 32.f);
}

// ---------------- launch ------------------------------------------------------
extern "C" void kernel_launch(void* const* d_in, const int* in_sizes, int n_in,
                              void* d_out, int out_size) {
    const float* x     = (const float*)d_in[0];
    const int*   tags  = (const int*)d_in[1];   // int32 (JAX x64 disabled)
    const int*   mask  = (const int*)d_in[2];
    const float* wihf  = (const float*)d_in[3];
    const float* whhf  = (const float*)d_in[4];
    const float* bf    = (const float*)d_in[5];
    const float* wihb  = (const float*)d_in[6];
    const float* whhb  = (const float*)d_in[7];
    const float* bb    = (const float*)d_in[8];
    const float* lng   = (const float*)d_in[9];
    const float* lnb   = (const float*)d_in[10];
    const float* Wt    = (const float*)d_in[11];
    const float* bt    = (const float*)d_in[12];
    const float* trans = (const float*)d_in[13];
    const float* st    = (const float*)d_in[14];
    const float* en    = (const float*)d_in[15];
    float* out = (float*)d_out;

    cudaFuncSetAttribute(lstm_persist_kernel,
                         cudaFuncAttributeMaxDynamicSharedMemorySize, PERSIST_SMEM);
    cudaFuncSetAttribute(proj_hmma_kernel,
                         cudaFuncAttributeMaxDynamicSharedMemorySize, PROJ_SMEM);

    cvt_x_kernel<<<8192, 256>>>(x);
    cvt_w_kernel<<<dim3(1024, 2), 256>>>(wihf, wihb);
    zero_cnt_kernel<<<1, 2>>>();
    proj_hmma_kernel<<<dim3(16, 128, 2), 256, PROJ_SMEM>>>(bf, bb);
    lstm_persist_kernel<<<128, 512, PERSIST_SMEM>>>(whhf, whhb);
    ln_emis_kernel<<<16384, 256>>>(lng, lnb, Wt, bt);
    crf_kernel<<<32, 32>>>(tags, mask, trans, st, en);
    final_kernel<<<1, 32>>>(out);
    (void)in_sizes; (void)n_in; (void)out_size;
}

// round 11
// speedup vs baseline: 2.5130x; 1.5020x over previous
#include <cuda_runtime.h>
#include <cuda_bf16.h>
#include <cstdint>

typedef unsigned long long ULL;

// ---------------- scratch (static device allocations; no cudaMalloc) -------
__device__ float g_xproj[67108864];           // [2][16384][2048] fp32
__device__ __nv_bfloat16 g_hb[16777216];      // h bf16 [b*512+t][1024] (fwd|bwd)
__device__ float g_emis[16384 * 32];
__device__ float g_llh[32];
__device__ unsigned g_cnt[2];
__device__ __nv_bfloat16 g_xb[16777216];      // X in bf16 [16384][1024]
__device__ __nv_bfloat16 g_wb[2][2097152];    // W_ih in bf16 [2][2048][1024]

// ---------------- helpers ---------------------------------------------------
__device__ __forceinline__ uint32_t smem_u32(const void* p) {
    uint32_t a;
    asm("{ .reg .u64 t; cvta.to.shared.u64 t, %1; cvt.u32.u64 %0, t; }" : "=r"(a) : "l"(p));
    return a;
}
__device__ __forceinline__ void cp16(uint32_t s, const void* g) {
    asm volatile("cp.async.cg.shared.global [%0], [%1], 16;" :: "r"(s), "l"(g));
}
#define CP_COMMIT() asm volatile("cp.async.commit_group;")
#define CP_WAIT(n)  asm volatile("cp.async.wait_group %0;" :: "n"(n))
#define LDSM_X4(r0, r1, r2, r3, addr) \
    asm volatile("ldmatrix.sync.aligned.m8n8.x4.shared.b16 {%0,%1,%2,%3}, [%4];" \
                 : "=r"(r0), "=r"(r1), "=r"(r2), "=r"(r3) : "r"(addr))
#define LDSM_X2(r0, r1, addr) \
    asm volatile("ldmatrix.sync.aligned.m8n8.x2.shared.b16 {%0,%1}, [%2];" \
                 : "=r"(r0), "=r"(r1) : "r"(addr))
#define MMA_BF16(c0, c1, c2, c3, a0, a1, a2, a3, b0, b1) \
    asm volatile("mma.sync.aligned.m16n8k16.row.col.f32.bf16.bf16.f32 " \
                 "{%0,%1,%2,%3}, {%4,%5,%6,%7}, {%8,%9}, {%0,%1,%2,%3};" \
                 : "+f"(c0), "+f"(c1), "+f"(c2), "+f"(c3) \
                 : "r"(a0), "r"(a1), "r"(a2), "r"(a3), "r"(b0), "r"(b1))

__device__ __forceinline__ uint4 pack8_bf16(const float* s) {
    __nv_bfloat162 p[4];
#pragma unroll
    for (int i = 0; i < 4; i++) {
        p[i].x = __float2bfloat16_rn(s[2 * i]);
        p[i].y = __float2bfloat16_rn(s[2 * i + 1]);
    }
    return *(uint4*)p;
}

// ---------------- 0) fp32 -> bf16 conversion prepass -------------------------
__global__ __launch_bounds__(256) void cvt_x_kernel(const float* __restrict__ x) {
    int i8 = (blockIdx.x * 256 + threadIdx.x) * 8;
    float v[8];
    *(float4*)v = *(const float4*)(x + i8);
    *(float4*)(v + 4) = *(const float4*)(x + i8 + 4);
    *(uint4*)(g_xb + i8) = pack8_bf16(v);
}
__global__ __launch_bounds__(256) void cvt_w_kernel(const float* __restrict__ wf,
                                                    const float* __restrict__ wb) {
    const float* w = blockIdx.y ? wb : wf;
    __nv_bfloat16* o = g_wb[blockIdx.y];
    int i8 = (blockIdx.x * 256 + threadIdx.x) * 8;
    float v[8];
    *(float4*)v = *(const float4*)(w + i8);
    *(float4*)(v + 4) = *(const float4*)(w + i8 + 4);
    *(uint4*)(o + i8) = pack8_bf16(v);
}

// ---------------- 1) input projection via HMMA mma.sync bf16 -----------------
#define PROJ_SMEM 65536

__global__ __launch_bounds__(256) void proj_hmma_kernel(
    const float* __restrict__ bf, const float* __restrict__ bb)
{
    extern __shared__ __align__(16) char psm[];
    const uint32_t sbase = smem_u32(psm);

    const int tid = threadIdx.x;
    const int wid = tid >> 5;
    const int lane = tid & 31;
    const int d = blockIdx.z;
    const int n0 = blockIdx.x * 128;
    const int m0 = blockIdx.y * 128;
    const __nv_bfloat16* Wb16 = g_wb[d];
    const float* bias = d ? bb : bf;
    float* C = g_xproj + (size_t)d * (16384ull * 2048ull);

    const int wm = wid >> 2;
    const int wn = wid & 3;

    float c[4][4][4];
#pragma unroll
    for (int mi = 0; mi < 4; mi++)
#pragma unroll
        for (int ni = 0; ni < 4; ni++)
#pragma unroll
            for (int q = 0; q < 4; q++) c[mi][ni][q] = 0.f;

#define STAGE(kc, buf) do { \
    _Pragma("unroll") \
    for (int i = 0; i < 4; i++) { \
        int u = tid + 256 * i; \
        int row = u >> 3, un = u & 7; \
        uint32_t sw = (uint32_t)((un ^ (row & 7)) * 16); \
        cp16(sbase + (buf) * 32768 + row * 128 + sw, \
             g_xb + (size_t)(m0 + row) * 1024 + (kc) * 64 + un * 8); \
        cp16(sbase + (buf) * 32768 + 16384 + row * 128 + sw, \
             Wb16 + (size_t)(n0 + row) * 1024 + (kc) * 64 + un * 8); \
    } \
    CP_COMMIT(); \
} while (0)

    STAGE(0, 0);
    for (int kc = 0; kc < 16; kc++) {
        const int buf = kc & 1;
        if (kc < 15) { STAGE(kc + 1, buf ^ 1); CP_WAIT(1); }
        else         { CP_WAIT(0); }
        __syncthreads();

        const uint32_t abase = sbase + buf * 32768;
        const uint32_t bbase = abase + 16384;
#pragma unroll
        for (int k16 = 0; k16 < 4; k16++) {
            uint32_t a[4][4];
#pragma unroll
            for (int mi = 0; mi < 4; mi++) {
                int row = wm * 64 + mi * 16 + (lane & 15);
                int un = k16 * 2 + (lane >> 4);
                uint32_t addr = abase + row * 128 + ((un ^ (row & 7)) * 16);
                LDSM_X4(a[mi][0], a[mi][1], a[mi][2], a[mi][3], addr);
            }
            uint32_t b[4][2];
#pragma unroll
            for (int ni = 0; ni < 4; ni++) {
                int row = wn * 32 + ni * 8 + (lane & 7);
                int un = k16 * 2 + ((lane >> 3) & 1);
                uint32_t addr = bbase + row * 128 + ((un ^ (row & 7)) * 16);
                LDSM_X2(b[ni][0], b[ni][1], addr);
            }
#pragma unroll
            for (int mi = 0; mi < 4; mi++)
#pragma unroll
                for (int ni = 0; ni < 4; ni++)
                    MMA_BF16(c[mi][ni][0], c[mi][ni][1], c[mi][ni][2], c[mi][ni][3],
                             a[mi][0], a[mi][1], a[mi][2], a[mi][3],
                             b[ni][0], b[ni][1]);
        }
        __syncthreads();
    }
#undef STAGE

#pragma unroll
    for (int ni = 0; ni < 4; ni++) {
        const int n = n0 + wn * 32 + ni * 8 + (lane & 3) * 2;
        const float bx = bias[n], by = bias[n + 1];
#pragma unroll
        for (int mi = 0; mi < 4; mi++) {
            const int m = m0 + wm * 64 + mi * 16 + (lane >> 2);
            float2 v0 = make_float2(c[mi][ni][0] + bx, c[mi][ni][1] + by);
            float2 v1 = make_float2(c[mi][ni][2] + bx, c[mi][ni][3] + by);
            *(float2*)(C + (size_t)m * 2048 + n) = v0;
            *(float2*)(C + (size_t)(m + 8) * 2048 + n) = v1;
        }
    }
}

// ---------------- counter reset ---------------------------------------------
__global__ void zero_cnt_kernel() { g_cnt[threadIdx.x] = 0u; }

// ---------------- 2) persistent BiLSTM recurrence, HMMA edition --------------
// 128 CTAs. blk>>6 = dir d, blk&63 = j (8 hidden units -> 32 gate rows).
// Weights: bf16 A-fragments resident in REGISTERS (16/thread) for all 512 steps.
// Per step: restage h (bf16, 32KB L2), ldmatrix B frags, 16 mma/warp,
// k-split partials in smem, reduce + xproj(fp32) + cell update, publish bf16 h.
//
// smem bytes: hs[32 batch][512 k] bf16 swizzled = 32768
//             part[16][32][32] fp32              = 65536 (also A staging at init)
//             gsum[32][33] fp32                  = 4224
#define HS_B    0
#define PART_B  32768
#define GSUM_B  (32768 + 65536)
#define PERSIST_SMEM (32768 + 65536 + 4224)

__global__ __launch_bounds__(512, 1) void lstm_persist_hmma_kernel(
    const float* __restrict__ whf, const float* __restrict__ whb)
{
    extern __shared__ __align__(16) char smc[];
    const uint32_t sbase = smem_u32(smc);
    const uint32_t hs_base = sbase + HS_B;
    const uint32_t ast_base = sbase + PART_B;       // A staging (init only)
    float* part = (float*)(smc + PART_B);
    float* gsum = (float*)(smc + GSUM_B);

    const int blk = blockIdx.x;
    const int d = blk >> 6;
    const int j = blk & 63;
    const int tid = threadIdx.x;
    const int warp = tid >> 5;
    const int lane = tid & 31;
    const float* w = d ? whb : whf;

    // ---- stage W_hh slice (fp32->bf16, swizzled) then load A fragments ------
#pragma unroll
    for (int it = 0; it < 4; it++) {
        int gidx = tid + 512 * it;                  // 0..2047 granules
        int lr = gidx >> 6;                         // 0..31 gate row
        int g = gidx & 63;                          // 16B granule in row
        int rowg = 512 * (lr >> 3) + 8 * j + (lr & 7);
        float v[8];
        *(float4*)v = *(const float4*)(w + (size_t)rowg * 512 + g * 8);
        *(float4*)(v + 4) = *(const float4*)(w + (size_t)rowg * 512 + g * 8 + 4);
        *(uint4*)(smc + PART_B + lr * 1024 + ((g ^ (lr & 7)) * 16)) = pack8_bf16(v);
    }
    __syncthreads();

    const int kw = warp * 32;                       // this warp's k range
    uint32_t afr[2][2][4];                          // [mi][kt][4]
    {
        const int q = lane >> 3;
#pragma unroll
        for (int mi = 0; mi < 2; mi++)
#pragma unroll
            for (int kt = 0; kt < 2; kt++) {
                int r = mi * 16 + (q & 1) * 8 + (lane & 7);
                int g = (kw + kt * 16) / 8 + (q >> 1);
                uint32_t addr = ast_base + r * 1024 + ((g ^ (r & 7)) * 16);
                LDSM_X4(afr[mi][kt][0], afr[mi][kt][1], afr[mi][kt][2], afr[mi][kt][3], addr);
            }
    }

    // ---- fixed B ldmatrix addresses (same every step) ------------------------
    uint32_t baddr[2][4];
    {
        const int l8 = lane & 7;
        const int lh = (lane >> 3) & 1;
#pragma unroll
        for (int kt = 0; kt < 2; kt++)
#pragma unroll
            for (int ni = 0; ni < 4; ni++) {
                int n = ni * 8 + l8;
                int g = kw / 8 + kt * 2 + lh;
                baddr[kt][ni] = hs_base + n * 1024 + ((g ^ (n & 7)) * 16);
            }
    }

    const float* xp = g_xproj + (size_t)d * (16384ull * 2048ull);
    const int o0 = tid, o1 = tid + 512;
    const int plr0 = o0 >> 5, pb0 = o0 & 31;
    const int plr1 = o1 >> 5, pb1 = o1 & 31;
    const int pg0 = 512 * (plr0 >> 3) + 8 * j + (plr0 & 7);
    const int pg1 = 512 * (plr1 >> 3) + 8 * j + (plr1 & 7);

    const int cu = tid & 7;
    const int cb = tid >> 3;
    float c_reg = 0.f;

    const int crow = lane >> 2;
    const int ccol = (lane & 3) * 2;

    volatile unsigned* cntp = &g_cnt[d];
    __syncthreads();

    for (int s = 0; s < 512; s++) {
        const int t = d ? (511 - s) : s;

        // prefetch xproj (DRAM) before the barrier spin
        float pf0 = xp[((size_t)pb0 * 512 + t) * 2048 + pg0];
        float pf1 = xp[((size_t)pb1 * 512 + t) * 2048 + pg1];

        if (s > 0) {
            if (tid == 0) {
                const unsigned target = 64u * (unsigned)s;
                while (*cntp < target) { }
                __threadfence();
            }
            __syncthreads();
            // restage h_prev (bf16) into swizzled smem
            const int tp = d ? (512 - s) : (s - 1);
#pragma unroll
            for (int it = 0; it < 4; it++) {
                int gidx = tid + 512 * it;          // 0..2047
                int n = gidx >> 6;
                int g = gidx & 63;
                uint4 v = __ldcg((const uint4*)(g_hb + ((size_t)n * 512 + tp) * 1024
                                                + d * 512 + g * 8));
                *(uint4*)(smc + HS_B + n * 1024 + ((g ^ (n & 7)) * 16)) = v;
            }
        } else {
            uint4 z = make_uint4(0u, 0u, 0u, 0u);
#pragma unroll
            for (int it = 0; it < 4; it++)
                ((uint4*)(smc + HS_B))[tid + 512 * it] = z;
        }
        __syncthreads();

        // ---- tensor GEMM: c = Whh_slice @ h ---------------------------------
        {
            uint32_t bfr[2][4][2];
#pragma unroll
            for (int kt = 0; kt < 2; kt++)
#pragma unroll
                for (int ni = 0; ni < 4; ni++)
                    LDSM_X2(bfr[kt][ni][0], bfr[kt][ni][1], baddr[kt][ni]);

            float c[2][4][4];
#pragma unroll
            for (int mi = 0; mi < 2; mi++)
#pragma unroll
                for (int ni = 0; ni < 4; ni++)
#pragma unroll
                    for (int q = 0; q < 4; q++) c[mi][ni][q] = 0.f;

#pragma unroll
            for (int mi = 0; mi < 2; mi++)
#pragma unroll
                for (int ni = 0; ni < 4; ni++)
#pragma unroll
                    for (int kt = 0; kt < 2; kt++)
                        MMA_BF16(c[mi][ni][0], c[mi][ni][1], c[mi][ni][2], c[mi][ni][3],
                                 afr[mi][kt][0], afr[mi][kt][1], afr[mi][kt][2], afr[mi][kt][3],
                                 bfr[kt][ni][0], bfr[kt][ni][1]);

            float* pw = part + warp * 1024;
#pragma unroll
            for (int mi = 0; mi < 2; mi++)
#pragma unroll
                for (int ni = 0; ni < 4; ni++) {
                    int r = mi * 16 + crow;
                    int cc = ni * 8 + ccol;
                    *(float2*)(pw + r * 32 + cc) = make_float2(c[mi][ni][0], c[mi][ni][1]);
                    *(float2*)(pw + (r + 8) * 32 + cc) = make_float2(c[mi][ni][2], c[mi][ni][3]);
                }
        }
        __syncthreads();

        // ---- reduce k-splits + add prefetched xproj -------------------------
        {
            float v0 = pf0, v1 = pf1;
#pragma unroll
            for (int kk = 0; kk < 16; kk++) v0 += part[kk * 1024 + o0];
#pragma unroll
            for (int kk = 0; kk < 16; kk++) v1 += part[kk * 1024 + o1];
            gsum[plr0 * 33 + pb0] = v0;
            gsum[plr1 * 33 + pb1] = v1;
        }
        __syncthreads();

        // ---- cell update (threads 0..255) -----------------------------------
        if (tid < 256) {
            float gi = gsum[(0 * 8 + cu) * 33 + cb];
            float gf = gsum[(1 * 8 + cu) * 33 + cb];
            float gg = gsum[(2 * 8 + cu) * 33 + cb];
            float go = gsum[(3 * 8 + cu) * 33 + cb];
            float si = 1.f / (1.f + __expf(-gi));
            float sf = 1.f / (1.f + __expf(-gf));
            float so = 1.f / (1.f + __expf(-go));
            float tg = tanhf(gg);
            c_reg = sf * c_reg + si * tg;
            float hv = so * tanhf(c_reg);
            g_hb[((size_t)cb * 512 + t) * 1024 + d * 512 + 8 * j + cu] =
                __float2bfloat16_rn(hv);
        }

        __threadfence();
        __syncthreads();
        if (tid == 0) atomicAdd(&g_cnt[d], 1u);
    }
}

// ---------------- 3) LayerNorm + emissions (bf16 h input) --------------------
__global__ __launch_bounds__(256) void ln_emis_kernel(
    const float* __restrict__ lng, const float* __restrict__ lnb,
    const float* __restrict__ Wt, const float* __restrict__ bt)
{
    __shared__ float shn[1024];
    __shared__ float red[16];
    const int row = blockIdx.x;
    const int tid = threadIdx.x;
    const __nv_bfloat16* hp = g_hb + (size_t)row * 1024;
    __nv_bfloat162 hv2[2];
    *(uint2*)hv2 = *(const uint2*)(hp + tid * 4);
    float vx = __bfloat162float(hv2[0].x), vy = __bfloat162float(hv2[0].y);
    float vz = __bfloat162float(hv2[1].x), vw = __bfloat162float(hv2[1].y);
    float s1 = vx + vy + vz + vw;
    float s2 = vx * vx + vy * vy + vz * vz + vw * vw;
#pragma unroll
    for (int o = 16; o; o >>= 1) {
        s1 += __shfl_down_sync(0xffffffffu, s1, o);
        s2 += __shfl_down_sync(0xffffffffu, s2, o);
    }
    const int w = tid >> 5, ln = tid & 31;
    if (ln == 0) { red[w] = s1; red[8 + w] = s2; }
    __syncthreads();
    if (tid == 0) {
        float a = 0.f, bq = 0.f;
#pragma unroll
        for (int i = 0; i < 8; i++) { a += red[i]; bq += red[8 + i]; }
        float mu = a * (1.f / 1024.f);
        float var = bq * (1.f / 1024.f) - mu * mu;
        red[0] = mu;
        red[1] = rsqrtf(var + 1e-5f);
    }
    __syncthreads();
    const float mu = red[0], rs = red[1];
    float4 g4 = *(const float4*)(lng + tid * 4);
    float4 b4 = *(const float4*)(lnb + tid * 4);
    shn[tid * 4 + 0] = (vx - mu) * rs * g4.x + b4.x;
    shn[tid * 4 + 1] = (vy - mu) * rs * g4.y + b4.y;
    shn[tid * 4 + 2] = (vz - mu) * rs * g4.z + b4.z;
    shn[tid * 4 + 3] = (vw - mu) * rs * g4.w + b4.w;
    __syncthreads();
#pragma unroll
    for (int tt = 0; tt < 4; tt++) {
        const int tag = w * 4 + tt;
        const float* wrow = Wt + (size_t)tag * 1024;
        float acc = 0.f;
#pragma unroll
        for (int i = 0; i < 32; i++) acc += shn[ln + 32 * i] * wrow[ln + 32 * i];
#pragma unroll
        for (int o = 16; o; o >>= 1) acc += __shfl_down_sync(0xffffffffu, acc, o);
        if (ln == 0) g_emis[(size_t)row * 32 + tag] = acc + bt[tag];
    }
}

// ---------------- 4) CRF log-likelihood (one warp per batch) -----------------
__global__ void crf_kernel(const int* __restrict__ tags,
                           const int* __restrict__ mask,
                           const float* __restrict__ trans,
                           const float* __restrict__ st,
                           const float* __restrict__ en)
{
    __shared__ float tr[32 * 33];
    const int b = blockIdx.x;
    const int jx = threadIdx.x;
    for (int i = jx; i < 1024; i += 32) tr[(i >> 5) * 33 + (i & 31)] = trans[i];
    __syncwarp();
    const float* eb = g_emis + (size_t)b * 512 * 32;
    const int* tg = tags + (size_t)b * 512;
    const int* mk = mask + (size_t)b * 512;

    float alpha = st[jx] + eb[jx];
    float np = 0.f;
    int ms = 0;
    for (int l = jx; l < 512; l += 32) {
        int m = mk[l];
        ms += m;
        if (l > 0 && m) {
            int tp = tg[l - 1], tc = tg[l];
            np += tr[tp * 33 + tc] + eb[l * 32 + tc];
        }
    }
    if (jx == 0) np += st[tg[0]] + eb[tg[0]];
#pragma unroll
    for (int o = 16; o; o >>= 1) {
        np += __shfl_xor_sync(0xffffffffu, np, o);
        ms += __shfl_xor_sync(0xffffffffu, ms, o);
    }
    const int lastidx = ms - 1;
    const float nend = en[tg[lastidx]];

    for (int l = 1; l < 512; l++) {
        float v[32];
        float mx = -1e30f;
#pragma unroll
        for (int i = 0; i < 32; i++) {
            float ai = __shfl_sync(0xffffffffu, alpha, i);
            v[i] = ai + tr[i * 33 + jx];
            mx = fmaxf(mx, v[i]);
        }
        float sa = 0.f;
#pragma unroll
        for (int i = 0; i < 32; i++) sa += __expf(v[i] - mx);
        float anew = mx + __logf(sa) + eb[l * 32 + jx];
        alpha = mk[l] ? anew : alpha;
    }
    float z = alpha + en[jx];
    float mz = z;
#pragma unroll
    for (int o = 16; o; o >>= 1) mz = fmaxf(mz, __shfl_xor_sync(0xffffffffu, mz, o));
    float sz = __expf(z - mz);
#pragma unroll
    for (int o = 16; o; o >>= 1) sz += __shfl_xor_sync(0xffffffffu, sz, o);
    float logZ = mz + __logf(sz);
    if (jx == 0) g_llh[b] = np + nend - logZ;
}

// ---------------- 5) final reduce --------------------------------------------
__global__ void final_kernel(float* out) {
    float v = g_llh[threadIdx.x];
#pragma unroll
    for (int o = 16; o; o >>= 1) v += __shfl_xor_sync(0xffffffffu, v, o);
    if (threadIdx.x == 0) out[0] = -v * (1.f / 32.f);
}

// ---------------- launch ------------------------------------------------------
extern "C" void kernel_launch(void* const* d_in, const int* in_sizes, int n_in,
                              void* d_out, int out_size) {
    const float* x     = (const float*)d_in[0];
    const int*   tags  = (const int*)d_in[1];   // int32 (JAX x64 disabled)
    const int*   mask  = (const int*)d_in[2];
    const float* wihf  = (const float*)d_in[3];
    const float* whhf  = (const float*)d_in[4];
    const float* bf    = (const float*)d_in[5];
    const float* wihb  = (const float*)d_in[6];
    const float* whhb  = (const float*)d_in[7];
    const float* bb    = (const float*)d_in[8];
    const float* lng   = (const float*)d_in[9];
    const float* lnb   = (const float*)d_in[10];
    const float* Wt    = (const float*)d_in[11];
    const float* bt    = (const float*)d_in[12];
    const float* trans = (const float*)d_in[13];
    const float* st    = (const float*)d_in[14];
    const float* en    = (const float*)d_in[15];
    float* out = (float*)d_out;

    cudaFuncSetAttribute(lstm_persist_hmma_kernel,
                         cudaFuncAttributeMaxDynamicSharedMemorySize, PERSIST_SMEM);
    cudaFuncSetAttribute(proj_hmma_kernel,
                         cudaFuncAttributeMaxDynamicSharedMemorySize, PROJ_SMEM);

    cvt_x_kernel<<<8192, 256>>>(x);
    cvt_w_kernel<<<dim3(1024, 2), 256>>>(wihf, wihb);
    zero_cnt_kernel<<<1, 2>>>();
    proj_hmma_kernel<<<dim3(16, 128, 2), 256, PROJ_SMEM>>>(bf, bb);
    lstm_persist_hmma_kernel<<<128, 512, PERSIST_SMEM>>>(whhf, whhb);
    ln_emis_kernel<<<16384, 256>>>(lng, lnb, Wt, bt);
    crf_kernel<<<32, 32>>>(tags, mask, trans, st, en);
    final_kernel<<<1, 32>>>(out);
    (void)in_sizes; (void)n_in; (void)out_size;
}

// round 14
// speedup vs baseline: 2.8528x; 1.1352x over previous
#include <cuda_runtime.h>
#include <cuda_bf16.h>
#include <cstdint>

typedef unsigned long long ULL;

// ---------------- scratch (static device allocations; no cudaMalloc) -------
__device__ float g_xproj[67108864];           // [2][16384][2048] fp32
__device__ __nv_bfloat16 g_hb[16777216];      // h bf16 [b*512+t][1024] (fwd|bwd)
__device__ float g_emis[16384 * 32];
__device__ float g_llh[32];
__device__ unsigned g_cnt[2];
__device__ __nv_bfloat16 g_xb[16777216];      // X in bf16 [16384][1024]
__device__ __nv_bfloat16 g_wb[2][2097152];    // W_ih in bf16 [2][2048][1024]
__device__ __nv_bfloat16 g_wtb[32768];        // W_tag bf16 [32][1024]

// ---------------- helpers ---------------------------------------------------
__device__ __forceinline__ uint32_t smem_u32(const void* p) {
    uint32_t a;
    asm("{ .reg .u64 t; cvta.to.shared.u64 t, %1; cvt.u32.u64 %0, t; }" : "=r"(a) : "l"(p));
    return a;
}
__device__ __forceinline__ void cp16(uint32_t s, const void* g) {
    asm volatile("cp.async.cg.shared.global [%0], [%1], 16;" :: "r"(s), "l"(g));
}
#define CP_COMMIT() asm volatile("cp.async.commit_group;")
#define CP_WAIT(n)  asm volatile("cp.async.wait_group %0;" :: "n"(n))
#define LDSM_X4(r0, r1, r2, r3, addr) \
    asm volatile("ldmatrix.sync.aligned.m8n8.x4.shared.b16 {%0,%1,%2,%3}, [%4];" \
                 : "=r"(r0), "=r"(r1), "=r"(r2), "=r"(r3) : "r"(addr))
#define LDSM_X2(r0, r1, addr) \
    asm volatile("ldmatrix.sync.aligned.m8n8.x2.shared.b16 {%0,%1}, [%2];" \
                 : "=r"(r0), "=r"(r1) : "r"(addr))
#define MMA_BF16(c0, c1, c2, c3, a0, a1, a2, a3, b0, b1) \
    asm volatile("mma.sync.aligned.m16n8k16.row.col.f32.bf16.bf16.f32 " \
                 "{%0,%1,%2,%3}, {%4,%5,%6,%7}, {%8,%9}, {%0,%1,%2,%3};" \
                 : "+f"(c0), "+f"(c1), "+f"(c2), "+f"(c3) \
                 : "r"(a0), "r"(a1), "r"(a2), "r"(a3), "r"(b0), "r"(b1))

__device__ __forceinline__ uint4 pack8_bf16(const float* s) {
    __nv_bfloat162 p[4];
#pragma unroll
    for (int i = 0; i < 4; i++) {
        p[i].x = __float2bfloat16_rn(s[2 * i]);
        p[i].y = __float2bfloat16_rn(s[2 * i + 1]);
    }
    return *(uint4*)p;
}

// ---------------- 0) fp32 -> bf16 conversion prepass -------------------------
__global__ __launch_bounds__(256) void cvt_x_kernel(const float* __restrict__ x) {
    int i8 = (blockIdx.x * 256 + threadIdx.x) * 8;
    float v[8];
    *(float4*)v = *(const float4*)(x + i8);
    *(float4*)(v + 4) = *(const float4*)(x + i8 + 4);
    *(uint4*)(g_xb + i8) = pack8_bf16(v);
}
__global__ __launch_bounds__(256) void cvt_w_kernel(const float* __restrict__ wf,
                                                    const float* __restrict__ wb) {
    const float* w = blockIdx.y ? wb : wf;
    __nv_bfloat16* o = g_wb[blockIdx.y];
    int i8 = (blockIdx.x * 256 + threadIdx.x) * 8;
    float v[8];
    *(float4*)v = *(const float4*)(w + i8);
    *(float4*)(v + 4) = *(const float4*)(w + i8 + 4);
    *(uint4*)(o + i8) = pack8_bf16(v);
}
__global__ __launch_bounds__(256) void cvt_wt_kernel(const float* __restrict__ wt) {
    int i8 = (blockIdx.x * 256 + threadIdx.x) * 8;
    float v[8];
    *(float4*)v = *(const float4*)(wt + i8);
    *(float4*)(v + 4) = *(const float4*)(wt + i8 + 4);
    *(uint4*)(g_wtb + i8) = pack8_bf16(v);
}

// ---------------- 1) input projection via HMMA mma.sync bf16 -----------------
#define PROJ_SMEM 65536

__global__ __launch_bounds__(256) void proj_hmma_kernel(
    const float* __restrict__ bf, const float* __restrict__ bb)
{
    extern __shared__ __align__(16) char psm[];
    const uint32_t sbase = smem_u32(psm);

    const int tid = threadIdx.x;
    const int wid = tid >> 5;
    const int lane = tid & 31;
    const int d = blockIdx.z;
    const int n0 = blockIdx.x * 128;
    const int m0 = blockIdx.y * 128;
    const __nv_bfloat16* Wb16 = g_wb[d];
    const float* bias = d ? bb : bf;
    float* C = g_xproj + (size_t)d * (16384ull * 2048ull);

    const int wm = wid >> 2;
    const int wn = wid & 3;

    float c[4][4][4];
#pragma unroll
    for (int mi = 0; mi < 4; mi++)
#pragma unroll
        for (int ni = 0; ni < 4; ni++)
#pragma unroll
            for (int q = 0; q < 4; q++) c[mi][ni][q] = 0.f;

#define STAGE(kc, buf) do { \
    _Pragma("unroll") \
    for (int i = 0; i < 4; i++) { \
        int u = tid + 256 * i; \
        int row = u >> 3, un = u & 7; \
        uint32_t sw = (uint32_t)((un ^ (row & 7)) * 16); \
        cp16(sbase + (buf) * 32768 + row * 128 + sw, \
             g_xb + (size_t)(m0 + row) * 1024 + (kc) * 64 + un * 8); \
        cp16(sbase + (buf) * 32768 + 16384 + row * 128 + sw, \
             Wb16 + (size_t)(n0 + row) * 1024 + (kc) * 64 + un * 8); \
    } \
    CP_COMMIT(); \
} while (0)

    STAGE(0, 0);
    for (int kc = 0; kc < 16; kc++) {
        const int buf = kc & 1;
        if (kc < 15) { STAGE(kc + 1, buf ^ 1); CP_WAIT(1); }
        else         { CP_WAIT(0); }
        __syncthreads();

        const uint32_t abase = sbase + buf * 32768;
        const uint32_t bbase = abase + 16384;
#pragma unroll
        for (int k16 = 0; k16 < 4; k16++) {
            uint32_t a[4][4];
#pragma unroll
            for (int mi = 0; mi < 4; mi++) {
                int row = wm * 64 + mi * 16 + (lane & 15);
                int un = k16 * 2 + (lane >> 4);
                uint32_t addr = abase + row * 128 + ((un ^ (row & 7)) * 16);
                LDSM_X4(a[mi][0], a[mi][1], a[mi][2], a[mi][3], addr);
            }
            uint32_t b[4][2];
#pragma unroll
            for (int ni = 0; ni < 4; ni++) {
                int row = wn * 32 + ni * 8 + (lane & 7);
                int un = k16 * 2 + ((lane >> 3) & 1);
                uint32_t addr = bbase + row * 128 + ((un ^ (row & 7)) * 16);
                LDSM_X2(b[ni][0], b[ni][1], addr);
            }
#pragma unroll
            for (int mi = 0; mi < 4; mi++)
#pragma unroll
                for (int ni = 0; ni < 4; ni++)
                    MMA_BF16(c[mi][ni][0], c[mi][ni][1], c[mi][ni][2], c[mi][ni][3],
                             a[mi][0], a[mi][1], a[mi][2], a[mi][3],
                             b[ni][0], b[ni][1]);
        }
        __syncthreads();
    }
#undef STAGE

#pragma unroll
    for (int ni = 0; ni < 4; ni++) {
        const int n = n0 + wn * 32 + ni * 8 + (lane & 3) * 2;
        const float bx = bias[n], by = bias[n + 1];
#pragma unroll
        for (int mi = 0; mi < 4; mi++) {
            const int m = m0 + wm * 64 + mi * 16 + (lane >> 2);
            float2 v0 = make_float2(c[mi][ni][0] + bx, c[mi][ni][1] + by);
            float2 v1 = make_float2(c[mi][ni][2] + bx, c[mi][ni][3] + by);
            *(float2*)(C + (size_t)m * 2048 + n) = v0;
            *(float2*)(C + (size_t)(m + 8) * 2048 + n) = v1;
        }
    }
}

// ---------------- counter reset ---------------------------------------------
__global__ void zero_cnt_kernel() { g_cnt[threadIdx.x] = 0u; }

// ---------------- 2) persistent BiLSTM recurrence, HMMA edition --------------
// 128 CTAs. blk>>6 = dir d, blk&63 = j (8 hidden units -> 32 gate rows).
// A (weights) in registers for all 512 steps. Per step: restage h bf16 -> smem
// (swizzled), ldmatrix B, 16 mma/warp, partials [kk][b*33+lr], paired-lane
// reduce + shfl gate exchange, cell update, release-atomic publish.
#define HS_B    0
#define PART_B  32768
#define PART_STRIDE 1056                       /* floats per kk slab (32*33) */
#define PERSIST_SMEM (32768 + 16 * PART_STRIDE * 4)

__global__ __launch_bounds__(512, 1) void lstm_persist_hmma_kernel(
    const float* __restrict__ whf, const float* __restrict__ whb)
{
    extern __shared__ __align__(16) char smc[];
    const uint32_t sbase = smem_u32(smc);
    const uint32_t hs_base = sbase + HS_B;
    const uint32_t ast_base = sbase + PART_B;       // A staging (init only)
    float* part = (float*)(smc + PART_B);

    const int blk = blockIdx.x;
    const int d = blk >> 6;
    const int j = blk & 63;
    const int tid = threadIdx.x;
    const int warp = tid >> 5;
    const int lane = tid & 31;
    const float* w = d ? whb : whf;

    // ---- stage W_hh slice (fp32->bf16, swizzled) then load A fragments ------
#pragma unroll
    for (int it = 0; it < 4; it++) {
        int gidx = tid + 512 * it;                  // 0..2047 granules
        int lr = gidx >> 6;                         // 0..31 gate row
        int g = gidx & 63;                          // 16B granule in row
        int rowg = 512 * (lr >> 3) + 8 * j + (lr & 7);
        float v[8];
        *(float4*)v = *(const float4*)(w + (size_t)rowg * 512 + g * 8);
        *(float4*)(v + 4) = *(const float4*)(w + (size_t)rowg * 512 + g * 8 + 4);
        *(uint4*)(smc + PART_B + lr * 1024 + ((g ^ (lr & 7)) * 16)) = pack8_bf16(v);
    }
    __syncthreads();

    const int kw = warp * 32;                       // this warp's k range
    uint32_t afr[2][2][4];                          // [mi][kt][4]
    {
        const int q = lane >> 3;
#pragma unroll
        for (int mi = 0; mi < 2; mi++)
#pragma unroll
            for (int kt = 0; kt < 2; kt++) {
                int r = mi * 16 + (q & 1) * 8 + (lane & 7);
                int g = (kw + kt * 16) / 8 + (q >> 1);
                uint32_t addr = ast_base + r * 1024 + ((g ^ (r & 7)) * 16);
                LDSM_X4(afr[mi][kt][0], afr[mi][kt][1], afr[mi][kt][2], afr[mi][kt][3], addr);
            }
    }

    // ---- fixed B ldmatrix addresses -----------------------------------------
    uint32_t baddr[2][4];
    {
        const int l8 = lane & 7;
        const int lh = (lane >> 3) & 1;
#pragma unroll
        for (int kt = 0; kt < 2; kt++)
#pragma unroll
            for (int ni = 0; ni < 4; ni++) {
                int n = ni * 8 + l8;
                int g = kw / 8 + kt * 2 + lh;
                baddr[kt][ni] = hs_base + n * 1024 + ((n & 7) ^ g) * 16;
            }
    }

    // ---- reduce/cell roles: paired lanes (lane, lane^16) own one (u,b) ------
    const int pair = warp * 16 + (lane & 15);       // 0..255
    const int cu = pair & 7;
    const int cb = pair >> 3;                       // 0..31
    const int half = lane >> 4;                     // 0: gates i,f  1: g,o
    const int lrA = cu + half * 16;
    const int lrB = cu + 8 + half * 16;
    const int qA = lrA >> 3, qB = lrB >> 3;
    const int growA = 512 * qA + 8 * j + cu;
    const int growB = 512 * qB + 8 * j + cu;
    const float* xp = g_xproj + (size_t)d * (16384ull * 2048ull);

    float c_reg = 0.f;                              // owned by half==0 threads
    const int crow = lane >> 2;
    const int ccol = (lane & 3) * 2;

    unsigned* cntp = &g_cnt[d];
    __syncthreads();

    for (int s = 0; s < 512; s++) {
        const int t = d ? (511 - s) : s;

        // prefetch xproj (DRAM) before the barrier spin
        float pfA = xp[((size_t)cb * 512 + t) * 2048 + growA];
        float pfB = xp[((size_t)cb * 512 + t) * 2048 + growB];

        if (s > 0) {
            if (tid == 0) {
                const unsigned target = 64u * (unsigned)s;
                unsigned v;
                do {
                    asm volatile("ld.acquire.gpu.u32 %0, [%1];" : "=r"(v) : "l"(cntp) : "memory");
                } while (v < target);
            }
            __syncthreads();
            // restage h_prev (bf16) into swizzled smem
            const int tp = d ? (512 - s) : (s - 1);
#pragma unroll
            for (int it = 0; it < 4; it++) {
                int gidx = tid + 512 * it;          // 0..2047
                int n = gidx >> 6;
                int g = gidx & 63;
                uint4 v = __ldcg((const uint4*)(g_hb + ((size_t)n * 512 + tp) * 1024
                                                + d * 512 + g * 8));
                *(uint4*)(smc + HS_B + n * 1024 + ((g ^ (n & 7)) * 16)) = v;
            }
        } else {
            uint4 z = make_uint4(0u, 0u, 0u, 0u);
#pragma unroll
            for (int it = 0; it < 4; it++)
                ((uint4*)(smc + HS_B))[tid + 512 * it] = z;
        }
        __syncthreads();

        // ---- tensor GEMM: c = Whh_slice @ h ---------------------------------
        {
            uint32_t bfr[2][4][2];
#pragma unroll
            for (int kt = 0; kt < 2; kt++)
#pragma unroll
                for (int ni = 0; ni < 4; ni++)
                    LDSM_X2(bfr[kt][ni][0], bfr[kt][ni][1], baddr[kt][ni]);

            float c[2][4][4];
#pragma unroll
            for (int mi = 0; mi < 2; mi++)
#pragma unroll
                for (int ni = 0; ni < 4; ni++)
#pragma unroll
                    for (int q = 0; q < 4; q++) c[mi][ni][q] = 0.f;

#pragma unroll
            for (int mi = 0; mi < 2; mi++)
#pragma unroll
                for (int ni = 0; ni < 4; ni++)
#pragma unroll
                    for (int kt = 0; kt < 2; kt++)
                        MMA_BF16(c[mi][ni][0], c[mi][ni][1], c[mi][ni][2], c[mi][ni][3],
                                 afr[mi][kt][0], afr[mi][kt][1], afr[mi][kt][2], afr[mi][kt][3],
                                 bfr[kt][ni][0], bfr[kt][ni][1]);

            // store partials: part[warp][b*33 + r]
            float* pw = part + warp * PART_STRIDE;
#pragma unroll
            for (int mi = 0; mi < 2; mi++)
#pragma unroll
                for (int ni = 0; ni < 4; ni++) {
                    const int r = mi * 16 + crow;
                    const int b0 = ni * 8 + ccol;
                    pw[b0 * 33 + r] = c[mi][ni][0];
                    pw[(b0 + 1) * 33 + r] = c[mi][ni][1];
                    pw[b0 * 33 + r + 8] = c[mi][ni][2];
                    pw[(b0 + 1) * 33 + r + 8] = c[mi][ni][3];
                }
        }
        __syncthreads();

        // ---- reduce k-splits (2 gate rows per thread) + shfl exchange -------
        {
            float vA = pfA, vB = pfB;
            const int oA = cb * 33 + lrA;
            const int oB = cb * 33 + lrB;
#pragma unroll
            for (int kk = 0; kk < 16; kk++) {
                vA += part[kk * PART_STRIDE + oA];
                vB += part[kk * PART_STRIDE + oB];
            }
            // half0 has (i,f); half1 has (g,o); exchange across lane^16
            float xg = __shfl_xor_sync(0xffffffffu, vA, 16);
            float xo = __shfl_xor_sync(0xffffffffu, vB, 16);
            if (half == 0) {
                float si = 1.f / (1.f + __expf(-vA));
                float sf = 1.f / (1.f + __expf(-vB));
                float so = 1.f / (1.f + __expf(-xo));
                float tg = tanhf(xg);
                c_reg = sf * c_reg + si * tg;
                float hv = so * tanhf(c_reg);
                g_hb[((size_t)cb * 512 + t) * 1024 + d * 512 + 8 * j + cu] =
                    __float2bfloat16_rn(hv);
            }
        }

        // ---- publish: bar orders h-stores; tid0 release-arrive --------------
        __syncthreads();
        if (tid == 0)
            asm volatile("red.release.gpu.add.u32 [%0], %1;" :: "l"(cntp), "r"(1u) : "memory");
    }
}

// ---------------- 3) LayerNorm + emissions (bf16 h, bf16 W_tag) --------------
__global__ __launch_bounds__(256) void ln_emis_kernel(
    const float* __restrict__ lng, const float* __restrict__ lnb,
    const float* __restrict__ bt)
{
    __shared__ float shn[1024];
    __shared__ float red[16];
    const int row = blockIdx.x;
    const int tid = threadIdx.x;
    const __nv_bfloat16* hp = g_hb + (size_t)row * 1024;
    __nv_bfloat162 hv2[2];
    *(uint2*)hv2 = *(const uint2*)(hp + tid * 4);
    float vx = __bfloat162float(hv2[0].x), vy = __bfloat162float(hv2[0].y);
    float vz = __bfloat162float(hv2[1].x), vw = __bfloat162float(hv2[1].y);
    float s1 = vx + vy + vz + vw;
    float s2 = vx * vx + vy * vy + vz * vz + vw * vw;
#pragma unroll
    for (int o = 16; o; o >>= 1) {
        s1 += __shfl_down_sync(0xffffffffu, s1, o);
        s2 += __shfl_down_sync(0xffffffffu, s2, o);
    }
    const int w = tid >> 5, ln = tid & 31;
    if (ln == 0) { red[w] = s1; red[8 + w] = s2; }
    __syncthreads();
    if (tid == 0) {
        float a = 0.f, bq = 0.f;
#pragma unroll
        for (int i = 0; i < 8; i++) { a += red[i]; bq += red[8 + i]; }
        float mu = a * (1.f / 1024.f);
        float var = bq * (1.f / 1024.f) - mu * mu;
        red[0] = mu;
        red[1] = rsqrtf(var + 1e-5f);
    }
    __syncthreads();
    const float mu = red[0], rs = red[1];
    float4 g4 = *(const float4*)(lng + tid * 4);
    float4 b4 = *(const float4*)(lnb + tid * 4);
    shn[tid * 4 + 0] = (vx - mu) * rs * g4.x + b4.x;
    shn[tid * 4 + 1] = (vy - mu) * rs * g4.y + b4.y;
    shn[tid * 4 + 2] = (vz - mu) * rs * g4.z + b4.z;
    shn[tid * 4 + 3] = (vw - mu) * rs * g4.w + b4.w;
    __syncthreads();
#pragma unroll
    for (int tt = 0; tt < 4; tt++) {
        const int tag = w * 4 + tt;
        const __nv_bfloat16* wrow = g_wtb + (size_t)tag * 1024;
        float acc = 0.f;
#pragma unroll
        for (int i = 0; i < 32; i++)
            acc += shn[ln + 32 * i] * __bfloat162float(wrow[ln + 32 * i]);
#pragma unroll
        for (int o = 16; o; o >>= 1) acc += __shfl_down_sync(0xffffffffu, acc, o);
        if (ln == 0) g_emis[(size_t)row * 32 + tag] = acc + bt[tag];
    }
}

// ---------------- 4) CRF log-likelihood (one warp per batch) -----------------
__global__ void crf_kernel(const int* __restrict__ tags,
                           const int* __restrict__ mask,
                           const float* __restrict__ trans,
                           const float* __restrict__ st,
                           const float* __restrict__ en)
{
    __shared__ float tr[32 * 33];
    const int b = blockIdx.x;
    const int jx = threadIdx.x;
    for (int i = jx; i < 1024; i += 32) tr[(i >> 5) * 33 + (i & 31)] = trans[i];
    __syncwarp();
    const float* eb = g_emis + (size_t)b * 512 * 32;
    const int* tg = tags + (size_t)b * 512;
    const int* mk = mask + (size_t)b * 512;

    float alpha = st[jx] + eb[jx];
    float np = 0.f;
    int ms = 0;
    for (int l = jx; l < 512; l += 32) {
        int m = mk[l];
        ms += m;
        if (l > 0 && m) {
            int tp = tg[l - 1], tc = tg[l];
            np += tr[tp * 33 + tc] + eb[l * 32 + tc];
        }
    }
    if (jx == 0) np += st[tg[0]] + eb[tg[0]];
#pragma unroll
    for (int o = 16; o; o >>= 1) {
        np += __shfl_xor_sync(0xffffffffu, np, o);
        ms += __shfl_xor_sync(0xffffffffu, ms, o);
    }
    const int lastidx = ms - 1;
    const float nend = en[tg[lastidx]];

    for (int l = 1; l < 512; l++) {
        float v[32];
        float mx = -1e30f;
#pragma unroll
        for (int i = 0; i < 32; i++) {
            float ai = __shfl_sync(0xffffffffu, alpha, i);
            v[i] = ai + tr[i * 33 + jx];
            mx = fmaxf(mx, v[i]);
        }
        float sa = 0.f;
#pragma unroll
        for (int i = 0; i < 32; i++) sa += __expf(v[i] - mx);
        float anew = mx + __logf(sa) + eb[l * 32 + jx];
        alpha = mk[l] ? anew : alpha;
    }
    float z = alpha + en[jx];
    float mz = z;
#pragma unroll
    for (int o = 16; o; o >>= 1) mz = fmaxf(mz, __shfl_xor_sync(0xffffffffu, mz, o));
    float sz = __expf(z - mz);
#pragma unroll
    for (int o = 16; o; o >>= 1) sz += __shfl_xor_sync(0xffffffffu, sz, o);
    float logZ = mz + __logf(sz);
    if (jx == 0) g_llh[b] = np + nend - logZ;
}

// ---------------- 5) final reduce --------------------------------------------
__global__ void final_kernel(float* out) {
    float v = g_llh[threadIdx.x];
#pragma unroll
    for (int o = 16; o; o >>= 1) v += __shfl_xor_sync(0xffffffffu, v, o);
    if (threadIdx.x == 0) out[0] = -v * (1.f / 32.f);
}

// ---------------- launch ------------------------------------------------------
extern "C" void kernel_launch(void* const* d_in, const int* in_sizes, int n_in,
                              void* d_out, int out_size) {
    const float* x     = (const float*)d_in[0];
    const int*   tags  = (const int*)d_in[1];   // int32 (JAX x64 disabled)
    const int*   mask  = (const int*)d_in[2];
    const float* wihf  = (const float*)d_in[3];
    const float* whhf  = (const float*)d_in[4];
    const float* bf    = (const float*)d_in[5];
    const float* wihb  = (const float*)d_in[6];
    const float* whhb  = (const float*)d_in[7];
    const float* bb    = (const float*)d_in[8];
    const float* lng   = (const float*)d_in[9];
    const float* lnb   = (const float*)d_in[10];
    const float* Wt    = (const float*)d_in[11];
    const float* bt    = (const float*)d_in[12];
    const float* trans = (const float*)d_in[13];
    const float* st    = (const float*)d_in[14];
    const float* en    = (const float*)d_in[15];
    float* out = (float*)d_out;

    cudaFuncSetAttribute(lstm_persist_hmma_kernel,
                         cudaFuncAttributeMaxDynamicSharedMemorySize, PERSIST_SMEM);
    cudaFuncSetAttribute(proj_hmma_kernel,
                         cudaFuncAttributeMaxDynamicSharedMemorySize, PROJ_SMEM);

    cvt_x_kernel<<<8192, 256>>>(x);
    cvt_w_kernel<<<dim3(1024, 2), 256>>>(wihf, wihb);
    cvt_wt_kernel<<<16, 256>>>(Wt);
    zero_cnt_kernel<<<1, 2>>>();
    proj_hmma_kernel<<<dim3(16, 128, 2), 256, PROJ_SMEM>>>(bf, bb);
    lstm_persist_hmma_kernel<<<128, 512, PERSIST_SMEM>>>(whhf, whhb);
    ln_emis_kernel<<<16384, 256>>>(lng, lnb, bt);
    crf_kernel<<<32, 32>>>(tags, mask, trans, st, en);
    final_kernel<<<1, 32>>>(out);
    (void)in_sizes; (void)n_in; (void)out_size;
}

// round 15
// speedup vs baseline: 4.2762x; 1.4990x over previous
#include <cuda_runtime.h>
#include <cuda_bf16.h>
#include <cstdint>

typedef unsigned long long ULL;

// ---------------- scratch (static device allocations; no cudaMalloc) -------
__device__ float g_xproj[67108864];           // [2][16384][2048] fp32
__device__ __nv_bfloat16 g_hb[16777216];      // h bf16 [b*512+t][1024] (fwd|bwd)
__device__ float g_emis[16384 * 32];
__device__ float g_llh[32];
__device__ unsigned g_cnt[8];                 // [d][batch-group]
__device__ __nv_bfloat16 g_xb[16777216];      // X in bf16 [16384][1024]
__device__ __nv_bfloat16 g_wb[2][2097152];    // W_ih in bf16 [2][2048][1024]
__device__ __nv_bfloat16 g_wtb[32768];        // W_tag bf16 [32][1024]

// ---------------- helpers ---------------------------------------------------
__device__ __forceinline__ uint32_t smem_u32(const void* p) {
    uint32_t a;
    asm("{ .reg .u64 t; cvta.to.shared.u64 t, %1; cvt.u32.u64 %0, t; }" : "=r"(a) : "l"(p));
    return a;
}
__device__ __forceinline__ void cp16(uint32_t s, const void* g) {
    asm volatile("cp.async.cg.shared.global [%0], [%1], 16;" :: "r"(s), "l"(g));
}
#define CP_COMMIT() asm volatile("cp.async.commit_group;")
#define CP_WAIT(n)  asm volatile("cp.async.wait_group %0;" :: "n"(n))
#define LDSM_X4(r0, r1, r2, r3, addr) \
    asm volatile("ldmatrix.sync.aligned.m8n8.x4.shared.b16 {%0,%1,%2,%3}, [%4];" \
                 : "=r"(r0), "=r"(r1), "=r"(r2), "=r"(r3) : "r"(addr))
#define LDSM_X2(r0, r1, addr) \
    asm volatile("ldmatrix.sync.aligned.m8n8.x2.shared.b16 {%0,%1}, [%2];" \
                 : "=r"(r0), "=r"(r1) : "r"(addr))
#define MMA_BF16(c0, c1, c2, c3, a0, a1, a2, a3, b0, b1) \
    asm volatile("mma.sync.aligned.m16n8k16.row.col.f32.bf16.bf16.f32 " \
                 "{%0,%1,%2,%3}, {%4,%5,%6,%7}, {%8,%9}, {%0,%1,%2,%3};" \
                 : "+f"(c0), "+f"(c1), "+f"(c2), "+f"(c3) \
                 : "r"(a0), "r"(a1), "r"(a2), "r"(a3), "r"(b0), "r"(b1))

__device__ __forceinline__ uint4 pack8_bf16(const float* s) {
    __nv_bfloat162 p[4];
#pragma unroll
    for (int i = 0; i < 4; i++) {
        p[i].x = __float2bfloat16_rn(s[2 * i]);
        p[i].y = __float2bfloat16_rn(s[2 * i + 1]);
    }
    return *(uint4*)p;
}

// ---------------- 0) fp32 -> bf16 conversion prepass -------------------------
__global__ __launch_bounds__(256) void cvt_x_kernel(const float* __restrict__ x) {
    if (blockIdx.x == 0 && threadIdx.x < 8) g_cnt[threadIdx.x] = 0u;
    int i8 = (blockIdx.x * 256 + threadIdx.x) * 8;
    float v[8];
    *(float4*)v = *(const float4*)(x + i8);
    *(float4*)(v + 4) = *(const float4*)(x + i8 + 4);
    *(uint4*)(g_xb + i8) = pack8_bf16(v);
}
__global__ __launch_bounds__(256) void cvt_w_kernel(const float* __restrict__ wf,
                                                    const float* __restrict__ wb) {
    const float* w = blockIdx.y ? wb : wf;
    __nv_bfloat16* o = g_wb[blockIdx.y];
    int i8 = (blockIdx.x * 256 + threadIdx.x) * 8;
    float v[8];
    *(float4*)v = *(const float4*)(w + i8);
    *(float4*)(v + 4) = *(const float4*)(w + i8 + 4);
    *(uint4*)(o + i8) = pack8_bf16(v);
}
__global__ __launch_bounds__(256) void cvt_wt_kernel(const float* __restrict__ wt) {
    int i8 = (blockIdx.x * 256 + threadIdx.x) * 8;
    float v[8];
    *(float4*)v = *(const float4*)(wt + i8);
    *(float4*)(v + 4) = *(const float4*)(wt + i8 + 4);
    *(uint4*)(g_wtb + i8) = pack8_bf16(v);
}

// ---------------- 1) input projection via HMMA mma.sync bf16 -----------------
#define PROJ_SMEM 65536

__global__ __launch_bounds__(256) void proj_hmma_kernel(
    const float* __restrict__ bf, const float* __restrict__ bb)
{
    extern __shared__ __align__(16) char psm[];
    const uint32_t sbase = smem_u32(psm);

    const int tid = threadIdx.x;
    const int wid = tid >> 5;
    const int lane = tid & 31;
    const int d = blockIdx.z;
    const int n0 = blockIdx.x * 128;
    const int m0 = blockIdx.y * 128;
    const __nv_bfloat16* Wb16 = g_wb[d];
    const float* bias = d ? bb : bf;
    float* C = g_xproj + (size_t)d * (16384ull * 2048ull);

    const int wm = wid >> 2;
    const int wn = wid & 3;

    float c[4][4][4];
#pragma unroll
    for (int mi = 0; mi < 4; mi++)
#pragma unroll
        for (int ni = 0; ni < 4; ni++)
#pragma unroll
            for (int q = 0; q < 4; q++) c[mi][ni][q] = 0.f;

#define STAGE(kc, buf) do { \
    _Pragma("unroll") \
    for (int i = 0; i < 4; i++) { \
        int u = tid + 256 * i; \
        int row = u >> 3, un = u & 7; \
        uint32_t sw = (uint32_t)((un ^ (row & 7)) * 16); \
        cp16(sbase + (buf) * 32768 + row * 128 + sw, \
             g_xb + (size_t)(m0 + row) * 1024 + (kc) * 64 + un * 8); \
        cp16(sbase + (buf) * 32768 + 16384 + row * 128 + sw, \
             Wb16 + (size_t)(n0 + row) * 1024 + (kc) * 64 + un * 8); \
    } \
    CP_COMMIT(); \
} while (0)

    STAGE(0, 0);
    for (int kc = 0; kc < 16; kc++) {
        const int buf = kc & 1;
        if (kc < 15) { STAGE(kc + 1, buf ^ 1); CP_WAIT(1); }
        else         { CP_WAIT(0); }
        __syncthreads();

        const uint32_t abase = sbase + buf * 32768;
        const uint32_t bbase = abase + 16384;
#pragma unroll
        for (int k16 = 0; k16 < 4; k16++) {
            uint32_t a[4][4];
#pragma unroll
            for (int mi = 0; mi < 4; mi++) {
                int row = wm * 64 + mi * 16 + (lane & 15);
                int un = k16 * 2 + (lane >> 4);
                uint32_t addr = abase + row * 128 + ((un ^ (row & 7)) * 16);
                LDSM_X4(a[mi][0], a[mi][1], a[mi][2], a[mi][3], addr);
            }
            uint32_t b[4][2];
#pragma unroll
            for (int ni = 0; ni < 4; ni++) {
                int row = wn * 32 + ni * 8 + (lane & 7);
                int un = k16 * 2 + ((lane >> 3) & 1);
                uint32_t addr = bbase + row * 128 + ((un ^ (row & 7)) * 16);
                LDSM_X2(b[ni][0], b[ni][1], addr);
            }
#pragma unroll
            for (int mi = 0; mi < 4; mi++)
#pragma unroll
                for (int ni = 0; ni < 4; ni++)
                    MMA_BF16(c[mi][ni][0], c[mi][ni][1], c[mi][ni][2], c[mi][ni][3],
                             a[mi][0], a[mi][1], a[mi][2], a[mi][3],
                             b[ni][0], b[ni][1]);
        }
        __syncthreads();
    }
#undef STAGE

#pragma unroll
    for (int ni = 0; ni < 4; ni++) {
        const int n = n0 + wn * 32 + ni * 8 + (lane & 3) * 2;
        const float bx = bias[n], by = bias[n + 1];
#pragma unroll
        for (int mi = 0; mi < 4; mi++) {
            const int m = m0 + wm * 64 + mi * 16 + (lane >> 2);
            float2 v0 = make_float2(c[mi][ni][0] + bx, c[mi][ni][1] + by);
            float2 v1 = make_float2(c[mi][ni][2] + bx, c[mi][ni][3] + by);
            *(float2*)(C + (size_t)m * 2048 + n) = v0;
            *(float2*)(C + (size_t)(m + 8) * 2048 + n) = v1;
        }
    }
}

// ---------------- 2) persistent BiLSTM recurrence, 2-D tiled -----------------
// 128 CTAs = d(2) x bg(4 batch-groups of 8) x hg(16 hidden-groups of 32 units).
// Per CTA-step: gates[128 rows x 8 b] = Whh_slice(128x512) @ h(512x8).
// A in registers (64/thread). Counter per (d,bg): fan-in 16. Restage 8KB/step.
#define PSLAB 1312                     /* floats per k-slab */
#define HS_B  0
#define PART_B 8192
#define PERSIST_SMEM 131072            /* A staging needs 128KB at init */

__global__ __launch_bounds__(512, 1) void lstm_persist_hmma_kernel(
    const float* __restrict__ whf, const float* __restrict__ whb)
{
    extern __shared__ __align__(16) char smc[];
    const uint32_t sbase = smem_u32(smc);
    const uint32_t hs_base = sbase + HS_B;
    const uint32_t ast_base = sbase;            // A staging aliases everything
    float* part = (float*)(smc + PART_B);

    const int blk = blockIdx.x;
    const int d = blk >> 6;
    const int bg = (blk >> 4) & 3;
    const int hg = blk & 15;
    const int tid = threadIdx.x;
    const int warp = tid >> 5;
    const int lane = tid & 31;
    const float* w = d ? whb : whf;

    // ---- stage W_hh slice (128 rows x 512 k, fp32->bf16, swizzled) ----------
#pragma unroll
    for (int it = 0; it < 16; it++) {
        int gi = tid + 512 * it;                // 0..8191 granules
        int r = gi >> 6;                        // 0..127 local gate row
        int g = gi & 63;
        int grow = 512 * (r >> 5) + hg * 32 + (r & 31);
        float v[8];
        *(float4*)v = *(const float4*)(w + (size_t)grow * 512 + g * 8);
        *(float4*)(v + 4) = *(const float4*)(w + (size_t)grow * 512 + g * 8 + 4);
        *(uint4*)(smc + r * 1024 + ((g ^ (r & 7)) * 16)) = pack8_bf16(v);
    }
    __syncthreads();

    const int ks = warp >> 1;                   // k-split 0..7 (k = ks*64)
    const int rh = warp & 1;                    // row half (64 rows)
    uint32_t afr[4][4][4];                      // [mi][kt][4] = 64 regs
    {
        const int q = lane >> 3;
#pragma unroll
        for (int mi = 0; mi < 4; mi++)
#pragma unroll
            for (int kt = 0; kt < 4; kt++) {
                int r = rh * 64 + mi * 16 + (q & 1) * 8 + (lane & 7);
                int g = ks * 8 + kt * 2 + (q >> 1);
                uint32_t addr = ast_base + r * 1024 + ((g ^ (r & 7)) * 16);
                LDSM_X4(afr[mi][kt][0], afr[mi][kt][1], afr[mi][kt][2], afr[mi][kt][3], addr);
            }
    }
    __syncthreads();                            // smem now reusable for hs/part

    // ---- fixed B ldmatrix addresses (8 batch rows x k) ----------------------
    uint32_t baddr[4];
    {
        const int l8 = lane & 7;
        const int lh = (lane >> 3) & 1;
#pragma unroll
        for (int kt = 0; kt < 4; kt++) {
            int g = ks * 8 + kt * 2 + lh;
            baddr[kt] = hs_base + l8 * 1024 + ((g ^ l8) * 16);
        }
    }

    // ---- reduce/cell roles: paired lanes (lane, lane^16) own one (u,b) ------
    const int pair = warp * 16 + (lane & 15);   // 0..255
    const int u = pair & 31;
    const int bb = pair >> 5;                   // 0..7 local batch
    const int half = lane >> 4;                 // 0: gates i,f  1: g,o
    const int qA = half * 2, qB = half * 2 + 1;
    const int lrA = qA * 32 + u, lrB = qB * 32 + u;
    const int growA = 512 * qA + hg * 32 + u;
    const int growB = 512 * qB + hg * 32 + u;
    const int gbatch = bg * 8 + bb;
    const int oA = bb * 164 + lrA + ((lrA >> 5) << 3);
    const int oB = bb * 164 + lrB + ((lrB >> 5) << 3);
    const float* xp = g_xproj + (size_t)d * (16384ull * 2048ull);

    float c_reg = 0.f;                          // owned by half==0 threads
    const int crow = lane >> 2;
    const int ccol = (lane & 3) * 2;

    // restage role: 1 granule per thread
    const int rb = tid >> 6;                    // 0..7 local batch row
    const int rg = tid & 63;
    const uint32_t rs_dst = hs_base + rb * 1024 + ((rg ^ rb) * 16);

    unsigned* cntp = &g_cnt[d * 4 + bg];

    for (int s = 0; s < 512; s++) {
        const int t = d ? (511 - s) : s;

        // prefetch xproj (DRAM) before the barrier spin
        float pfA = xp[((size_t)gbatch * 512 + t) * 2048 + growA];
        float pfB = xp[((size_t)gbatch * 512 + t) * 2048 + growB];

        if (s > 0) {
            if (tid == 0) {
                const unsigned target = 16u * (unsigned)s;
                unsigned v;
                do {
                    asm volatile("ld.acquire.gpu.u32 %0, [%1];" : "=r"(v) : "l"(cntp) : "memory");
                } while (v < target);
            }
            __syncthreads();
            const int tp = d ? (512 - s) : (s - 1);
            uint4 v = __ldcg((const uint4*)(g_hb + ((size_t)(bg * 8 + rb) * 512 + tp) * 1024
                                            + d * 512 + rg * 8));
            *(uint4*)(size_t)rs_dst;            // address compute kept hot
            *(uint4*)(smc + HS_B + rb * 1024 + ((rg ^ rb) * 16)) = v;
        } else {
            ((uint4*)(smc + HS_B))[tid] = make_uint4(0u, 0u, 0u, 0u);
        }
        __syncthreads();

        // ---- tensor GEMM: c = Whh_slice @ h ---------------------------------
        {
            uint32_t bfr[4][2];
#pragma unroll
            for (int kt = 0; kt < 4; kt++)
                LDSM_X2(bfr[kt][0], bfr[kt][1], baddr[kt]);

            float c[4][4];
#pragma unroll
            for (int mi = 0; mi < 4; mi++)
#pragma unroll
                for (int q = 0; q < 4; q++) c[mi][q] = 0.f;

#pragma unroll
            for (int mi = 0; mi < 4; mi++)
#pragma unroll
                for (int kt = 0; kt < 4; kt++)
                    MMA_BF16(c[mi][0], c[mi][1], c[mi][2], c[mi][3],
                             afr[mi][kt][0], afr[mi][kt][1], afr[mi][kt][2], afr[mi][kt][3],
                             bfr[kt][0], bfr[kt][1]);

            float* pw = part + ks * PSLAB;
#pragma unroll
            for (int mi = 0; mi < 4; mi++) {
                const int rbase = rh * 64 + mi * 16;
                const int skew = (rbase >> 5) << 3;
                const int r = rbase + crow + skew;
                pw[ccol * 164 + r] = c[mi][0];
                pw[(ccol + 1) * 164 + r] = c[mi][1];
                pw[ccol * 164 + r + 8] = c[mi][2];
                pw[(ccol + 1) * 164 + r + 8] = c[mi][3];
            }
        }
        __syncthreads();

        // ---- reduce 8 k-slabs + cell update ---------------------------------
        {
            float vA = pfA, vB = pfB;
#pragma unroll
            for (int kk = 0; kk < 8; kk++) {
                vA += part[kk * PSLAB + oA];
                vB += part[kk * PSLAB + oB];
            }
            float xg = __shfl_xor_sync(0xffffffffu, vA, 16);
            float xo = __shfl_xor_sync(0xffffffffu, vB, 16);
            if (half == 0) {
                float si = 1.f / (1.f + __expf(-vA));
                float sf = 1.f / (1.f + __expf(-vB));
                float so = 1.f / (1.f + __expf(-xo));
                float tg = tanhf(xg);
                c_reg = sf * c_reg + si * tg;
                float hv = so * tanhf(c_reg);
                g_hb[((size_t)gbatch * 512 + t) * 1024 + d * 512 + hg * 32 + u] =
                    __float2bfloat16_rn(hv);
            }
        }

        __syncthreads();
        if (tid == 0)
            asm volatile("red.release.gpu.add.u32 [%0], %1;" :: "l"(cntp), "r"(1u) : "memory");
    }
}

// ---------------- 3) LayerNorm + emissions (bf16 h, bf16 W_tag) --------------
__global__ __launch_bounds__(256) void ln_emis_kernel(
    const float* __restrict__ lng, const float* __restrict__ lnb,
    const float* __restrict__ bt)
{
    __shared__ float shn[1024];
    __shared__ float red[16];
    const int row = blockIdx.x;
    const int tid = threadIdx.x;
    const __nv_bfloat16* hp = g_hb + (size_t)row * 1024;
    __nv_bfloat162 hv2[2];
    *(uint2*)hv2 = *(const uint2*)(hp + tid * 4);
    float vx = __bfloat162float(hv2[0].x), vy = __bfloat162float(hv2[0].y);
    float vz = __bfloat162float(hv2[1].x), vw = __bfloat162float(hv2[1].y);
    float s1 = vx + vy + vz + vw;
    float s2 = vx * vx + vy * vy + vz * vz + vw * vw;
#pragma unroll
    for (int o = 16; o; o >>= 1) {
        s1 += __shfl_down_sync(0xffffffffu, s1, o);
        s2 += __shfl_down_sync(0xffffffffu, s2, o);
    }
    const int w = tid >> 5, ln = tid & 31;
    if (ln == 0) { red[w] = s1; red[8 + w] = s2; }
    __syncthreads();
    if (tid == 0) {
        float a = 0.f, bq = 0.f;
#pragma unroll
        for (int i = 0; i < 8; i++) { a += red[i]; bq += red[8 + i]; }
        float mu = a * (1.f / 1024.f);
        float var = bq * (1.f / 1024.f) - mu * mu;
        red[0] = mu;
        red[1] = rsqrtf(var + 1e-5f);
    }
    __syncthreads();
    const float mu = red[0], rs = red[1];
    float4 g4 = *(const float4*)(lng + tid * 4);
    float4 b4 = *(const float4*)(lnb + tid * 4);
    shn[tid * 4 + 0] = (vx - mu) * rs * g4.x + b4.x;
    shn[tid * 4 + 1] = (vy - mu) * rs * g4.y + b4.y;
    shn[tid * 4 + 2] = (vz - mu) * rs * g4.z + b4.z;
    shn[tid * 4 + 3] = (vw - mu) * rs * g4.w + b4.w;
    __syncthreads();
#pragma unroll
    for (int tt = 0; tt < 4; tt++) {
        const int tag = w * 4 + tt;
        const __nv_bfloat16* wrow = g_wtb + (size_t)tag * 1024;
        float acc = 0.f;
#pragma unroll
        for (int i = 0; i < 32; i++)
            acc += shn[ln + 32 * i] * __bfloat162float(wrow[ln + 32 * i]);
#pragma unroll
        for (int o = 16; o; o >>= 1) acc += __shfl_down_sync(0xffffffffu, acc, o);
        if (ln == 0) g_emis[(size_t)row * 32 + tag] = acc + bt[tag];
    }
}

// ---------------- 4) CRF log-likelihood (one warp per batch) -----------------
__global__ void crf_kernel(const int* __restrict__ tags,
                           const int* __restrict__ mask,
                           const float* __restrict__ trans,
                           const float* __restrict__ st,
                           const float* __restrict__ en)
{
    __shared__ float tr[32 * 33];
    const int b = blockIdx.x;
    const int jx = threadIdx.x;
    for (int i = jx; i < 1024; i += 32) tr[(i >> 5) * 33 + (i & 31)] = trans[i];
    __syncwarp();
    const float* eb = g_emis + (size_t)b * 512 * 32;
    const int* tg = tags + (size_t)b * 512;
    const int* mk = mask + (size_t)b * 512;

    float alpha = st[jx] + eb[jx];
    float np = 0.f;
    int ms = 0;
    for (int l = jx; l < 512; l += 32) {
        int m = mk[l];
        ms += m;
        if (l > 0 && m) {
            int tp = tg[l - 1], tc = tg[l];
            np += tr[tp * 33 + tc] + eb[l * 32 + tc];
        }
    }
    if (jx == 0) np += st[tg[0]] + eb[tg[0]];
#pragma unroll
    for (int o = 16; o; o >>= 1) {
        np += __shfl_xor_sync(0xffffffffu, np, o);
        ms += __shfl_xor_sync(0xffffffffu, ms, o);
    }
    const int lastidx = ms - 1;
    const float nend = en[tg[lastidx]];

    for (int l = 1; l < 512; l++) {
        float v[32];
        float mx = -1e30f;
#pragma unroll
        for (int i = 0; i < 32; i++) {
            float ai = __shfl_sync(0xffffffffu, alpha, i);
            v[i] = ai + tr[i * 33 + jx];
            mx = fmaxf(mx, v[i]);
        }
        float sa = 0.f;
#pragma unroll
        for (int i = 0; i < 32; i++) sa += __expf(v[i] - mx);
        float anew = mx + __logf(sa) + eb[l * 32 + jx];
        alpha = mk[l] ? anew : alpha;
    }
    float z = alpha + en[jx];
    float mz = z;
#pragma unroll
    for (int o = 16; o; o >>= 1) mz = fmaxf(mz, __shfl_xor_sync(0xffffffffu, mz, o));
    float sz = __expf(z - mz);
#pragma unroll
    for (int o = 16; o; o >>= 1) sz += __shfl_xor_sync(0xffffffffu, sz, o);
    float logZ = mz + __logf(sz);
    if (jx == 0) g_llh[b] = np + nend - logZ;
}

// ---------------- 5) final reduce --------------------------------------------
__global__ void final_kernel(float* out) {
    float v = g_llh[threadIdx.x];
#pragma unroll
    for (int o = 16; o; o >>= 1) v += __shfl_xor_sync(0xffffffffu, v, o);
    if (threadIdx.x == 0) out[0] = -v * (1.f / 32.f);
}

// ---------------- launch ------------------------------------------------------
extern "C" void kernel_launch(void* const* d_in, const int* in_sizes, int n_in,
                              void* d_out, int out_size) {
    const float* x     = (const float*)d_in[0];
    const int*   tags  = (const int*)d_in[1];   // int32 (JAX x64 disabled)
    const int*   mask  = (const int*)d_in[2];
    const float* wihf  = (const float*)d_in[3];
    const float* whhf  = (const float*)d_in[4];
    const float* bf    = (const float*)d_in[5];
    const float* wihb  = (const float*)d_in[6];
    const float* whhb  = (const float*)d_in[7];
    const float* bb    = (const float*)d_in[8];
    const float* lng   = (const float*)d_in[9];
    const float* lnb   = (const float*)d_in[10];
    const float* Wt    = (const float*)d_in[11];
    const float* bt    = (const float*)d_in[12];
    const float* trans = (const float*)d_in[13];
    const float* st    = (const float*)d_in[14];
    const float* en    = (const float*)d_in[15];
    float* out = (float*)d_out;

    cudaFuncSetAttribute(lstm_persist_hmma_kernel,
                         cudaFuncAttributeMaxDynamicSharedMemorySize, PERSIST_SMEM);
    cudaFuncSetAttribute(proj_hmma_kernel,
                         cudaFuncAttributeMaxDynamicSharedMemorySize, PROJ_SMEM);

    cvt_x_kernel<<<8192, 256>>>(x);
    cvt_w_kernel<<<dim3(1024, 2), 256>>>(wihf, wihb);
    cvt_wt_kernel<<<16, 256>>>(Wt);
    proj_hmma_kernel<<<dim3(16, 128, 2), 256, PROJ_SMEM>>>(bf, bb);
    lstm_persist_hmma_kernel<<<128, 512, PERSIST_SMEM>>>(whhf, whhb);
    ln_emis_kernel<<<16384, 256>>>(lng, lnb, bt);
    crf_kernel<<<32, 32>>>(tags, mask, trans, st, en);
    final_kernel<<<1, 32>>>(out);
    (void)in_sizes; (void)n_in; (void)out_size;
}